// round 1
// baseline (speedup 1.0000x reference)
#include <cuda_runtime.h>
#include <math.h>

#define TT 256
#define BB 256
#define FF 128
#define HH 384
#define LL 3
#define KKW 10
#define GG 1542
#define SS 64
// C = HH/LL = 128

// ---------------- persistent scratch (static device allocations) ----------------
static __device__ float g_xk[TT * BB * GG];      // precomputed x@Wk + all biases (404 MB)
static __device__ float g_xo[BB * GG];           // per-step pre-activations
static __device__ float g_c[BB * HH];            // cell state
static __device__ float g_h[BB * HH];            // hidden state
static __device__ float g_hist_h[KKW * BB * HH]; // rolling h buffer (slot = t % K)
static __device__ float g_hist_d[KKW * BB];      // rolling cur_d buffer
static __device__ float g_dis[BB * KKW];
static __device__ float g_wh[KKW * BB * HH];     // local_h weighted: wh[k][b][i]
static __device__ float g_M[BB * HH];            // mean over k of local_h
static __device__ float g_P[BB * SS];
static __device__ float g_theme[BB * HH];
static __device__ float g_conv[BB * HH];
static __device__ float g_bias[GG];
static __device__ float g_wct[KKW * HH * HH];    // Wc transposed to [(k*H+i)][o]

__device__ __forceinline__ float sigmoidf(float x) { return 1.0f / (1.0f + expf(-x)); }

// ---------------- small setup kernels ----------------
__global__ void bias_kernel(const float* __restrict__ Wk, const float* __restrict__ bk,
                            const float* __restrict__ Wr, const float* __restrict__ br) {
    int j = blockIdx.x * blockDim.x + threadIdx.x;
    if (j < GG) g_bias[j] = bk[j] + br[j] + Wk[FF * GG + j] + Wr[HH * GG + j];
}

__global__ void init_state_kernel() {
    int i = blockIdx.x * blockDim.x + threadIdx.x;
    if (i < BB * HH) { g_c[i] = 0.0f; g_h[i] = 0.0f; }
}

__global__ void wct_kernel(const float* __restrict__ Wc) {
    int idx = blockIdx.x * blockDim.x + threadIdx.x;  // over KKW*HH*HH
    if (idx >= KKW * HH * HH) return;
    int kkidx = idx / HH;        // k*HH + i
    int o = idx - kkidx * HH;
    int k = kkidx / HH;
    int i = kkidx - k * HH;
    g_wct[idx] = Wc[(o * HH + i) * KKW + k];
}

// ---------------- generic fp32 GEMM: C[M,N] = A[M,K]@B[K,N] (+bias[col]) (+add[row,col]) ----------
// Assumes ldb == N (true for Wk/Wr with N=GG), M % 64 == 0, K % 16 == 0. Only N needs guards.
__global__ __launch_bounds__(256) void sgemm64(
    const float* __restrict__ A, const float* __restrict__ Bm, float* __restrict__ C,
    int M, int N, int Kd, const float* __restrict__ bias, const float* __restrict__ add)
{
    __shared__ float As[64][17];
    __shared__ float Bs[16][64];
    const int tx = threadIdx.x & 15;
    const int ty = threadIdx.x >> 4;
    const int row0 = blockIdx.y * 64;
    const int col0 = blockIdx.x * 64;
    float acc[4][4] = {};
    for (int k0 = 0; k0 < Kd; k0 += 16) {
        #pragma unroll
        for (int i = threadIdx.x; i < 64 * 16; i += 256) {
            int r = i >> 4, kk = i & 15;
            As[r][kk] = A[(row0 + r) * Kd + k0 + kk];
        }
        #pragma unroll
        for (int i = threadIdx.x; i < 16 * 64; i += 256) {
            int kk = i >> 6, cc = i & 63;
            Bs[kk][cc] = Bm[(size_t)(k0 + kk) * N + col0 + cc];  // OOB cols read into next row (exists)
        }
        __syncthreads();
        #pragma unroll
        for (int kk = 0; kk < 16; kk++) {
            float av[4], bv[4];
            #pragma unroll
            for (int m = 0; m < 4; m++) av[m] = As[ty * 4 + m][kk];
            #pragma unroll
            for (int n = 0; n < 4; n++) bv[n] = Bs[kk][tx * 4 + n];
            #pragma unroll
            for (int m = 0; m < 4; m++)
                #pragma unroll
                for (int n = 0; n < 4; n++)
                    acc[m][n] += av[m] * bv[n];
        }
        __syncthreads();
    }
    #pragma unroll
    for (int m = 0; m < 4; m++) {
        int row = row0 + ty * 4 + m;
        #pragma unroll
        for (int n = 0; n < 4; n++) {
            int col = col0 + tx * 4 + n;
            if (col < N) {
                float v = acc[m][n];
                if (bias) v += bias[col];
                if (add)  v += add[(size_t)row * N + col];
                C[(size_t)row * N + col] = v;
            }
        }
    }
}

// ---------------- per-step gate / state update ----------------
// grid: BB blocks of HH threads. tid = l*128 + c.
__global__ __launch_bounds__(HH) void gates_kernel(int t) {
    int b = blockIdx.x;
    int tid = threadIdx.x;
    __shared__ float sfm[LL], sim[LL], scd;
    if (tid == 0) {
        const float* xo = g_xo + b * GG;
        float a0 = xo[0], a1 = xo[1], a2 = xo[2];
        float m = fmaxf(a0, fmaxf(a1, a2));
        float e0 = expf(a0 - m), e1 = expf(a1 - m), e2 = expf(a2 - m);
        float s = e0 + e1 + e2;
        float p0 = e0 / s, p1 = e1 / s;
        sfm[0] = p0; sfm[1] = p0 + p1; sfm[2] = 1.0f;
        float b0 = xo[3], b1 = xo[4], b2 = xo[5];
        m = fmaxf(b0, fmaxf(b1, b2));
        e0 = expf(b0 - m); e1 = expf(b1 - m); e2 = expf(b2 - m);
        s = e0 + e1 + e2;
        float q1 = e1 / s, q2 = e2 / s;
        sim[0] = 1.0f; sim[1] = q1 + q2; sim[2] = q2;  // suffix sums of softmax
        scd = 1.0f - (sfm[0] + sfm[1] + sfm[2]) * (1.0f / 3.0f);
    }
    __syncthreads();
    int l = tid >> 7;  // tid / 128
    const float* xo = g_xo + b * GG + 2 * LL;
    float fg = sigmoidf(xo[0 * HH + tid]);
    float ig = sigmoidf(xo[1 * HH + tid]);
    float og = sigmoidf(xo[2 * HH + tid]);
    float ci = tanhf(xo[3 * HH + tid]);
    float co = g_c[b * HH + tid];
    float fm = sfm[l], im = sim[l], ov = fm * im;
    float cn = co * (ov * fg + fm - ov) + ci * (ov * ig + im - ov);
    float hn = og * tanhf(cn);
    g_c[b * HH + tid] = cn;
    g_h[b * HH + tid] = hn;
    if (t >= TT - KKW) {
        g_hist_h[(t % KKW) * BB * HH + b * HH + tid] = hn;
        if (tid == 0) g_hist_d[(t % KKW) * BB + b] = scd;
    }
}

// ---------------- final head (runs once) ----------------
__global__ void dis_kernel() {
    int b = threadIdx.x;  // 256 threads, 1 block
    if (b >= BB) return;
    float cum = 0.0f, v[KKW];
    #pragma unroll
    for (int k = 0; k < KKW; k++) {
        int slot = (TT - KKW + k) % KKW;
        cum += g_hist_d[slot * BB + b];
        v[k] = cum;
    }
    float m = v[0];
    #pragma unroll
    for (int k = 1; k < KKW; k++) m = fmaxf(m, v[k]);
    float s = 0.0f;
    #pragma unroll
    for (int k = 0; k < KKW; k++) { v[k] = expf(v[k] - m); s += v[k]; }
    float inv = 1.0f / s;
    #pragma unroll
    for (int k = 0; k < KKW; k++) g_dis[b * KKW + k] = v[k] * inv;
}

__global__ void wh_kernel() {
    int idx = blockIdx.x * blockDim.x + threadIdx.x;  // over BB*HH
    if (idx >= BB * HH) return;
    int b = idx / HH;
    float acc = 0.0f;
    #pragma unroll
    for (int k = 0; k < KKW; k++) {
        int slot = (TT - KKW + k) % KKW;
        float v = g_hist_h[slot * BB * HH + idx] * g_dis[b * KKW + k];
        g_wh[k * BB * HH + idx] = v;
        acc += v;
    }
    g_M[idx] = acc * (1.0f / KKW);
}

// conv[b,o] = sum_{k,i} wh[k][b][i] * Wc[o,i,k] + bc[o]; K-dim flattened as kkidx=k*HH+i (3840)
__global__ __launch_bounds__(256) void conv_kernel(const float* __restrict__ bc) {
    __shared__ float Asm[16][65];  // [kk][bb]
    __shared__ float Bsm[16][64];  // [kk][oo]
    const int tx = threadIdx.x & 15;
    const int ty = threadIdx.x >> 4;
    const int b0 = blockIdx.y * 64;
    const int o0 = blockIdx.x * 64;
    float acc[4][4] = {};
    const int KD = KKW * HH;  // 3840
    for (int kk0 = 0; kk0 < KD; kk0 += 16) {
        #pragma unroll
        for (int x2 = threadIdx.x; x2 < 64 * 16; x2 += 256) {
            int bb = x2 >> 4, kk = x2 & 15;
            int kkidx = kk0 + kk;
            int k = kkidx / HH, i = kkidx - k * HH;
            Asm[kk][bb] = g_wh[k * BB * HH + (b0 + bb) * HH + i];
        }
        #pragma unroll
        for (int x2 = threadIdx.x; x2 < 16 * 64; x2 += 256) {
            int kk = x2 >> 6, oo = x2 & 63;
            Bsm[kk][oo] = g_wct[(size_t)(kk0 + kk) * HH + o0 + oo];
        }
        __syncthreads();
        #pragma unroll
        for (int kk = 0; kk < 16; kk++) {
            float av[4], bv[4];
            #pragma unroll
            for (int m = 0; m < 4; m++) av[m] = Asm[kk][ty * 4 + m];
            #pragma unroll
            for (int n = 0; n < 4; n++) bv[n] = Bsm[kk][tx * 4 + n];
            #pragma unroll
            for (int m = 0; m < 4; m++)
                #pragma unroll
                for (int n = 0; n < 4; n++)
                    acc[m][n] += av[m] * bv[n];
        }
        __syncthreads();
    }
    #pragma unroll
    for (int m = 0; m < 4; m++) {
        int b = b0 + ty * 4 + m;
        #pragma unroll
        for (int n = 0; n < 4; n++) {
            int o = o0 + tx * 4 + n;
            g_conv[b * HH + o] = acc[m][n] + bc[o];
        }
    }
}

__global__ void p_kernel(const float* __restrict__ Ws, const float* __restrict__ bs) {
    int b = blockIdx.x;
    int s2 = threadIdx.x;  // SS threads
    float acc = bs[s2];
    for (int i = 0; i < HH; i++) acc += g_M[b * HH + i] * Ws[i * SS + s2];
    g_P[b * SS + s2] = fmaxf(acc, 0.0f);
}

__global__ void theme_kernel(const float* __restrict__ Wrs, const float* __restrict__ brs) {
    int b = blockIdx.x;
    int o = threadIdx.x;  // HH threads
    float acc = brs[o];
    #pragma unroll 8
    for (int s2 = 0; s2 < SS; s2++) acc += g_P[b * SS + s2] * Wrs[s2 * HH + o];
    g_theme[b * HH + o] = sigmoidf(acc);
}

__global__ void out_kernel(const float* __restrict__ Wo, const float* __restrict__ bo,
                           float* __restrict__ out) {
    int b = blockIdx.x;
    __shared__ float red[128];
    float acc = 0.0f;
    for (int i = threadIdx.x; i < HH; i += 128) {
        float rnn = g_theme[b * HH + i] * g_conv[b * HH + i] + g_h[b * HH + i];
        acc += rnn * Wo[i];
    }
    red[threadIdx.x] = acc;
    __syncthreads();
    for (int s = 64; s > 0; s >>= 1) {
        if (threadIdx.x < s) red[threadIdx.x] += red[threadIdx.x + s];
        __syncthreads();
    }
    if (threadIdx.x == 0) out[b] = sigmoidf(red[0] + bo[0]);
}

// ---------------- host launcher (graph-capturable: launches only) ----------------
extern "C" void kernel_launch(void* const* d_in, const int* in_sizes, int n_in,
                              void* d_out, int out_size)
{
    (void)in_sizes; (void)n_in; (void)out_size;
    const float* x   = (const float*)d_in[0];
    const float* Wk  = (const float*)d_in[1];
    const float* bk  = (const float*)d_in[2];
    const float* Wr  = (const float*)d_in[3];
    const float* br  = (const float*)d_in[4];
    const float* Ws  = (const float*)d_in[5];
    const float* bs  = (const float*)d_in[6];
    const float* Wrs = (const float*)d_in[7];
    const float* brs = (const float*)d_in[8];
    const float* Wc  = (const float*)d_in[9];
    const float* bc  = (const float*)d_in[10];
    const float* Wo  = (const float*)d_in[11];
    const float* bo  = (const float*)d_in[12];

    float *p_xk, *p_xo, *p_h, *p_bias;
    cudaGetSymbolAddress((void**)&p_xk, g_xk);
    cudaGetSymbolAddress((void**)&p_xo, g_xo);
    cudaGetSymbolAddress((void**)&p_h, g_h);
    cudaGetSymbolAddress((void**)&p_bias, g_bias);

    bias_kernel<<<(GG + 255) / 256, 256>>>(Wk, bk, Wr, br);
    init_state_kernel<<<(BB * HH + 255) / 256, 256>>>();
    wct_kernel<<<(KKW * HH * HH + 255) / 256, 256>>>(Wc);

    // Hoisted non-recurrent GEMM: g_xk[t,b,:] = x[t,b,:]@Wk[:F] + (bk+br+Wk[F]+Wr[H])
    {
        dim3 grid((GG + 63) / 64, (TT * BB) / 64);
        sgemm64<<<grid, 256>>>(x, Wk, p_xk, TT * BB, GG, FF, p_bias, nullptr);
    }

    // Sequential recurrence: only h@Wr remains on the critical path
    for (int t = 0; t < TT; t++) {
        dim3 grid((GG + 63) / 64, BB / 64);
        sgemm64<<<grid, 256>>>(p_h, Wr, p_xo, BB, GG, HH, nullptr,
                               p_xk + (size_t)t * BB * GG);
        gates_kernel<<<BB, HH>>>(t);
    }

    // Final head: only evaluated at t = T-1
    dis_kernel<<<1, 256>>>();
    wh_kernel<<<(BB * HH + 255) / 256, 256>>>();
    conv_kernel<<<dim3(HH / 64, BB / 64), 256>>>(bc);
    p_kernel<<<BB, SS>>>(Ws, bs);
    theme_kernel<<<BB, HH>>>(Wrs, brs);
    out_kernel<<<BB, 128>>>(Wo, bo, (float*)d_out);
}

// round 2
// speedup vs baseline: 1.0001x; 1.0001x over previous
#include <cuda_runtime.h>
#include <math.h>

#define TT 256
#define BB 256
#define FF 128
#define HH 384
#define LL 3
#define KKW 10
#define GG 1542
#define SS 64
// C = HH/LL = 128

// ---------------- persistent scratch (static device allocations) ----------------
static __device__ float g_xk[TT * BB * GG];      // precomputed x@Wk + all biases (404 MB)
static __device__ float g_xo[BB * GG];           // per-step pre-activations
static __device__ float g_c[BB * HH];            // cell state
static __device__ float g_h[BB * HH];            // hidden state
static __device__ float g_hist_h[KKW * BB * HH]; // rolling h buffer (slot = t % K)
static __device__ float g_hist_d[KKW * BB];      // rolling cur_d buffer
static __device__ float g_dis[BB * KKW];
static __device__ float g_wh[KKW * BB * HH];     // local_h weighted: wh[k][b][i]
static __device__ float g_M[BB * HH];            // mean over k of local_h
static __device__ float g_P[BB * SS];
static __device__ float g_theme[BB * HH];
static __device__ float g_conv[BB * HH];
static __device__ float g_bias[GG];
static __device__ float g_wct[KKW * HH * HH];    // Wc transposed to [(k*H+i)][o]

__device__ __forceinline__ float sigmoidf(float x) { return 1.0f / (1.0f + expf(-x)); }

// ---------------- small setup kernels ----------------
__global__ void bias_kernel(const float* __restrict__ Wk, const float* __restrict__ bk,
                            const float* __restrict__ Wr, const float* __restrict__ br) {
    int j = blockIdx.x * blockDim.x + threadIdx.x;
    if (j < GG) g_bias[j] = bk[j] + br[j] + Wk[FF * GG + j] + Wr[HH * GG + j];
}

__global__ void init_state_kernel() {
    int i = blockIdx.x * blockDim.x + threadIdx.x;
    if (i < BB * HH) { g_c[i] = 0.0f; g_h[i] = 0.0f; }
}

__global__ void wct_kernel(const float* __restrict__ Wc) {
    int idx = blockIdx.x * blockDim.x + threadIdx.x;  // over KKW*HH*HH
    if (idx >= KKW * HH * HH) return;
    int kkidx = idx / HH;        // k*HH + i
    int o = idx - kkidx * HH;
    int k = kkidx / HH;
    int i = kkidx - k * HH;
    g_wct[idx] = Wc[(o * HH + i) * KKW + k];
}

// ---------------- generic fp32 GEMM: C[M,N] = A[M,K]@B[K,N] (+bias[col]) (+add[row,col]) ----------
// Assumes ldb == N (true for Wk/Wr with N=GG), M % 64 == 0, K % 16 == 0. Only N needs guards.
__global__ __launch_bounds__(256) void sgemm64(
    const float* __restrict__ A, const float* __restrict__ Bm, float* __restrict__ C,
    int M, int N, int Kd, const float* __restrict__ bias, const float* __restrict__ add)
{
    __shared__ float As[64][17];
    __shared__ float Bs[16][64];
    const int tx = threadIdx.x & 15;
    const int ty = threadIdx.x >> 4;
    const int row0 = blockIdx.y * 64;
    const int col0 = blockIdx.x * 64;
    float acc[4][4] = {};
    for (int k0 = 0; k0 < Kd; k0 += 16) {
        #pragma unroll
        for (int i = threadIdx.x; i < 64 * 16; i += 256) {
            int r = i >> 4, kk = i & 15;
            As[r][kk] = A[(row0 + r) * Kd + k0 + kk];
        }
        #pragma unroll
        for (int i = threadIdx.x; i < 16 * 64; i += 256) {
            int kk = i >> 6, cc = i & 63;
            Bs[kk][cc] = Bm[(size_t)(k0 + kk) * N + col0 + cc];  // OOB cols read into next row (exists)
        }
        __syncthreads();
        #pragma unroll
        for (int kk = 0; kk < 16; kk++) {
            float av[4], bv[4];
            #pragma unroll
            for (int m = 0; m < 4; m++) av[m] = As[ty * 4 + m][kk];
            #pragma unroll
            for (int n = 0; n < 4; n++) bv[n] = Bs[kk][tx * 4 + n];
            #pragma unroll
            for (int m = 0; m < 4; m++)
                #pragma unroll
                for (int n = 0; n < 4; n++)
                    acc[m][n] += av[m] * bv[n];
        }
        __syncthreads();
    }
    #pragma unroll
    for (int m = 0; m < 4; m++) {
        int row = row0 + ty * 4 + m;
        #pragma unroll
        for (int n = 0; n < 4; n++) {
            int col = col0 + tx * 4 + n;
            if (col < N) {
                float v = acc[m][n];
                if (bias) v += bias[col];
                if (add)  v += add[(size_t)row * N + col];
                C[(size_t)row * N + col] = v;
            }
        }
    }
}

// ---------------- per-step gate / state update ----------------
// grid: BB blocks of HH threads. tid = l*128 + c.
__global__ __launch_bounds__(HH) void gates_kernel(int t) {
    int b = blockIdx.x;
    int tid = threadIdx.x;
    __shared__ float sfm[LL], sim[LL], scd;
    if (tid == 0) {
        const float* xo = g_xo + b * GG;
        float a0 = xo[0], a1 = xo[1], a2 = xo[2];
        float m = fmaxf(a0, fmaxf(a1, a2));
        float e0 = expf(a0 - m), e1 = expf(a1 - m), e2 = expf(a2 - m);
        float s = e0 + e1 + e2;
        float p0 = e0 / s, p1 = e1 / s;
        sfm[0] = p0; sfm[1] = p0 + p1; sfm[2] = 1.0f;
        float b0 = xo[3], b1 = xo[4], b2 = xo[5];
        m = fmaxf(b0, fmaxf(b1, b2));
        e0 = expf(b0 - m); e1 = expf(b1 - m); e2 = expf(b2 - m);
        s = e0 + e1 + e2;
        float q1 = e1 / s, q2 = e2 / s;
        sim[0] = 1.0f; sim[1] = q1 + q2; sim[2] = q2;  // suffix sums of softmax
        scd = 1.0f - (sfm[0] + sfm[1] + sfm[2]) * (1.0f / 3.0f);
    }
    __syncthreads();
    int l = tid >> 7;  // tid / 128
    const float* xo = g_xo + b * GG + 2 * LL;
    float fg = sigmoidf(xo[0 * HH + tid]);
    float ig = sigmoidf(xo[1 * HH + tid]);
    float og = sigmoidf(xo[2 * HH + tid]);
    float ci = tanhf(xo[3 * HH + tid]);
    float co = g_c[b * HH + tid];
    float fm = sfm[l], im = sim[l], ov = fm * im;
    float cn = co * (ov * fg + fm - ov) + ci * (ov * ig + im - ov);
    float hn = og * tanhf(cn);
    g_c[b * HH + tid] = cn;
    g_h[b * HH + tid] = hn;
    if (t >= TT - KKW) {
        g_hist_h[(t % KKW) * BB * HH + b * HH + tid] = hn;
        if (tid == 0) g_hist_d[(t % KKW) * BB + b] = scd;
    }
}

// ---------------- final head (runs once) ----------------
__global__ void dis_kernel() {
    int b = threadIdx.x;  // 256 threads, 1 block
    if (b >= BB) return;
    float cum = 0.0f, v[KKW];
    #pragma unroll
    for (int k = 0; k < KKW; k++) {
        int slot = (TT - KKW + k) % KKW;
        cum += g_hist_d[slot * BB + b];
        v[k] = cum;
    }
    float m = v[0];
    #pragma unroll
    for (int k = 1; k < KKW; k++) m = fmaxf(m, v[k]);
    float s = 0.0f;
    #pragma unroll
    for (int k = 0; k < KKW; k++) { v[k] = expf(v[k] - m); s += v[k]; }
    float inv = 1.0f / s;
    #pragma unroll
    for (int k = 0; k < KKW; k++) g_dis[b * KKW + k] = v[k] * inv;
}

__global__ void wh_kernel() {
    int idx = blockIdx.x * blockDim.x + threadIdx.x;  // over BB*HH
    if (idx >= BB * HH) return;
    int b = idx / HH;
    float acc = 0.0f;
    #pragma unroll
    for (int k = 0; k < KKW; k++) {
        int slot = (TT - KKW + k) % KKW;
        float v = g_hist_h[slot * BB * HH + idx] * g_dis[b * KKW + k];
        g_wh[k * BB * HH + idx] = v;
        acc += v;
    }
    g_M[idx] = acc * (1.0f / KKW);
}

// conv[b,o] = sum_{k,i} wh[k][b][i] * Wc[o,i,k] + bc[o]; K-dim flattened as kkidx=k*HH+i (3840)
__global__ __launch_bounds__(256) void conv_kernel(const float* __restrict__ bc) {
    __shared__ float Asm[16][65];  // [kk][bb]
    __shared__ float Bsm[16][64];  // [kk][oo]
    const int tx = threadIdx.x & 15;
    const int ty = threadIdx.x >> 4;
    const int b0 = blockIdx.y * 64;
    const int o0 = blockIdx.x * 64;
    float acc[4][4] = {};
    const int KD = KKW * HH;  // 3840
    for (int kk0 = 0; kk0 < KD; kk0 += 16) {
        #pragma unroll
        for (int x2 = threadIdx.x; x2 < 64 * 16; x2 += 256) {
            int bb = x2 >> 4, kk = x2 & 15;
            int kkidx = kk0 + kk;
            int k = kkidx / HH, i = kkidx - k * HH;
            Asm[kk][bb] = g_wh[k * BB * HH + (b0 + bb) * HH + i];
        }
        #pragma unroll
        for (int x2 = threadIdx.x; x2 < 16 * 64; x2 += 256) {
            int kk = x2 >> 6, oo = x2 & 63;
            Bsm[kk][oo] = g_wct[(size_t)(kk0 + kk) * HH + o0 + oo];
        }
        __syncthreads();
        #pragma unroll
        for (int kk = 0; kk < 16; kk++) {
            float av[4], bv[4];
            #pragma unroll
            for (int m = 0; m < 4; m++) av[m] = Asm[kk][ty * 4 + m];
            #pragma unroll
            for (int n = 0; n < 4; n++) bv[n] = Bsm[kk][tx * 4 + n];
            #pragma unroll
            for (int m = 0; m < 4; m++)
                #pragma unroll
                for (int n = 0; n < 4; n++)
                    acc[m][n] += av[m] * bv[n];
        }
        __syncthreads();
    }
    #pragma unroll
    for (int m = 0; m < 4; m++) {
        int b = b0 + ty * 4 + m;
        #pragma unroll
        for (int n = 0; n < 4; n++) {
            int o = o0 + tx * 4 + n;
            g_conv[b * HH + o] = acc[m][n] + bc[o];
        }
    }
}

__global__ void p_kernel(const float* __restrict__ Ws, const float* __restrict__ bs) {
    int b = blockIdx.x;
    int s2 = threadIdx.x;  // SS threads
    float acc = bs[s2];
    for (int i = 0; i < HH; i++) acc += g_M[b * HH + i] * Ws[i * SS + s2];
    g_P[b * SS + s2] = fmaxf(acc, 0.0f);
}

__global__ void theme_kernel(const float* __restrict__ Wrs, const float* __restrict__ brs) {
    int b = blockIdx.x;
    int o = threadIdx.x;  // HH threads
    float acc = brs[o];
    #pragma unroll 8
    for (int s2 = 0; s2 < SS; s2++) acc += g_P[b * SS + s2] * Wrs[s2 * HH + o];
    g_theme[b * HH + o] = sigmoidf(acc);
}

__global__ void out_kernel(const float* __restrict__ Wo, const float* __restrict__ bo,
                           float* __restrict__ out) {
    int b = blockIdx.x;
    __shared__ float red[128];
    float acc = 0.0f;
    for (int i = threadIdx.x; i < HH; i += 128) {
        float rnn = g_theme[b * HH + i] * g_conv[b * HH + i] + g_h[b * HH + i];
        acc += rnn * Wo[i];
    }
    red[threadIdx.x] = acc;
    __syncthreads();
    for (int s = 64; s > 0; s >>= 1) {
        if (threadIdx.x < s) red[threadIdx.x] += red[threadIdx.x + s];
        __syncthreads();
    }
    if (threadIdx.x == 0) out[b] = sigmoidf(red[0] + bo[0]);
}

// ---------------- host launcher (graph-capturable: launches only) ----------------
extern "C" void kernel_launch(void* const* d_in, const int* in_sizes, int n_in,
                              void* d_out, int out_size)
{
    (void)in_sizes; (void)n_in; (void)out_size;
    const float* x   = (const float*)d_in[0];
    const float* Wk  = (const float*)d_in[1];
    const float* bk  = (const float*)d_in[2];
    const float* Wr  = (const float*)d_in[3];
    const float* br  = (const float*)d_in[4];
    const float* Ws  = (const float*)d_in[5];
    const float* bs  = (const float*)d_in[6];
    const float* Wrs = (const float*)d_in[7];
    const float* brs = (const float*)d_in[8];
    const float* Wc  = (const float*)d_in[9];
    const float* bc  = (const float*)d_in[10];
    const float* Wo  = (const float*)d_in[11];
    const float* bo  = (const float*)d_in[12];

    float *p_xk, *p_xo, *p_h, *p_bias;
    cudaGetSymbolAddress((void**)&p_xk, g_xk);
    cudaGetSymbolAddress((void**)&p_xo, g_xo);
    cudaGetSymbolAddress((void**)&p_h, g_h);
    cudaGetSymbolAddress((void**)&p_bias, g_bias);

    bias_kernel<<<(GG + 255) / 256, 256>>>(Wk, bk, Wr, br);
    init_state_kernel<<<(BB * HH + 255) / 256, 256>>>();
    wct_kernel<<<(KKW * HH * HH + 255) / 256, 256>>>(Wc);

    // Hoisted non-recurrent GEMM: g_xk[t,b,:] = x[t,b,:]@Wk[:F] + (bk+br+Wk[F]+Wr[H])
    {
        dim3 grid((GG + 63) / 64, (TT * BB) / 64);
        sgemm64<<<grid, 256>>>(x, Wk, p_xk, TT * BB, GG, FF, p_bias, nullptr);
    }

    // Sequential recurrence: only h@Wr remains on the critical path
    for (int t = 0; t < TT; t++) {
        dim3 grid((GG + 63) / 64, BB / 64);
        sgemm64<<<grid, 256>>>(p_h, Wr, p_xo, BB, GG, HH, nullptr,
                               p_xk + (size_t)t * BB * GG);
        gates_kernel<<<BB, HH>>>(t);
    }

    // Final head: only evaluated at t = T-1
    dis_kernel<<<1, 256>>>();
    wh_kernel<<<(BB * HH + 255) / 256, 256>>>();
    conv_kernel<<<dim3(HH / 64, BB / 64), 256>>>(bc);
    p_kernel<<<BB, SS>>>(Ws, bs);
    theme_kernel<<<BB, HH>>>(Wrs, brs);
    out_kernel<<<BB, 128>>>(Wo, bo, (float*)d_out);
}

// round 3
// speedup vs baseline: 2.0488x; 2.0486x over previous
#include <cuda_runtime.h>
#include <math.h>

#define TT 256
#define BB 256
#define FF 128
#define HH 384
#define LL 3
#define KKW 10
#define GG 1542
#define SS 64

#define NBLK 96
#define JC 4
#define NCOL 22
#define NPAD 24
#define NT 3
#define WRS 40
#define AST 36
#define XOS 25
#define KC 32
#define NCHUNK 12
#define SMEM_BYTES ((384*WRS + 3*256*AST + 256*XOS)*4)

static __device__ float g_xkT[(size_t)TT * GG * BB];  // [t][g][b]
static __device__ float g_xT[(size_t)TT * FF * BB];   // [t][f][b]
static __device__ float g_h2[2][BB * HH];
static __device__ float g_hist_h[KKW * BB * HH];
static __device__ float g_hist_d[KKW * BB];
static __device__ float g_dis[BB * KKW];
static __device__ float g_wh[KKW * BB * HH];
static __device__ float g_M[BB * HH];
static __device__ float g_P[BB * SS];
static __device__ float g_theme[BB * HH];
static __device__ float g_conv[BB * HH];
static __device__ float g_bias[GG];
static __device__ float g_wct[KKW * HH * HH];
static __device__ unsigned g_arrive;

__device__ __forceinline__ float sigmoidf(float x) { return 1.0f / (1.0f + expf(-x)); }
__device__ __forceinline__ int gcol(int n, int j0) {
    return (n < 6) ? n : 6 + ((n - 6) >> 2) * HH + j0 + ((n - 6) & 3);
}
__device__ __forceinline__ unsigned f2tf32(float x) {
    unsigned u; asm("cvt.rna.tf32.f32 %0, %1;" : "=r"(u) : "f"(x)); return u;
}
__device__ __forceinline__ void mma8(float* d, const unsigned* a, const unsigned* b) {
    asm volatile("mma.sync.aligned.m16n8k8.row.col.f32.tf32.tf32.f32 "
                 "{%0,%1,%2,%3}, {%4,%5,%6,%7}, {%8,%9}, {%0,%1,%2,%3};"
                 : "+f"(d[0]), "+f"(d[1]), "+f"(d[2]), "+f"(d[3])
                 : "r"(a[0]), "r"(a[1]), "r"(a[2]), "r"(a[3]), "r"(b[0]), "r"(b[1]));
}
__device__ __forceinline__ void cp16(float* s, const float* g) {
    unsigned sa = (unsigned)__cvta_generic_to_shared(s);
    asm volatile("cp.async.cg.shared.global [%0], [%1], 16;" :: "r"(sa), "l"(g));
}

// ---------- setup ----------
__global__ void bias_kernel(const float* __restrict__ Wk, const float* __restrict__ bk,
                            const float* __restrict__ Wr, const float* __restrict__ br) {
    int j = blockIdx.x * blockDim.x + threadIdx.x;
    if (j < GG) g_bias[j] = bk[j] + br[j] + Wk[FF * GG + j] + Wr[HH * GG + j];
}
__global__ void init_state_kernel() {
    int i = blockIdx.x * blockDim.x + threadIdx.x;
    if (i < BB * HH) g_h2[0][i] = 0.0f;
    if (i == 0) g_arrive = 0u;
}
__global__ void wct_kernel(const float* __restrict__ Wc) {
    int idx = blockIdx.x * blockDim.x + threadIdx.x;
    if (idx >= KKW * HH * HH) return;
    int kkidx = idx / HH, o = idx - kkidx * HH;
    int k = kkidx / HH, i = kkidx - k * HH;
    g_wct[idx] = Wc[(o * HH + i) * KKW + k];
}
__global__ void xT_kernel(const float* __restrict__ x) {
    __shared__ float tile[32][33];
    int t = blockIdx.z, f0 = blockIdx.x * 32, b0 = blockIdx.y * 32;
    int tx = threadIdx.x, ty = threadIdx.y;
    #pragma unroll
    for (int i = 0; i < 4; i++)
        tile[ty + 8 * i][tx] = x[((size_t)t * BB + b0 + ty + 8 * i) * FF + f0 + tx];
    __syncthreads();
    #pragma unroll
    for (int i = 0; i < 4; i++)
        g_xT[((size_t)t * FF + f0 + ty + 8 * i) * BB + b0 + tx] = tile[tx][ty + 8 * i];
}

// ---------- precompute: g_xkT[t][g][b] = sum_k Wk[k][g]*x[t][b][k] + bias[g] ----------
__global__ __launch_bounds__(256) void sgemmT(const float* __restrict__ Wk) {
    __shared__ float As[64][17];
    __shared__ float Bs[16][64];
    const int t = blockIdx.z, m0 = blockIdx.y * 64, n0 = blockIdx.x * 64;
    const int tx = threadIdx.x & 15, ty = threadIdx.x >> 4;
    float acc[4][4] = {};
    for (int k0 = 0; k0 < FF; k0 += 16) {
        #pragma unroll
        for (int i = threadIdx.x; i < 1024; i += 256) {
            int kk = i >> 6, r = i & 63, g = m0 + r;
            As[r][kk] = (g < GG) ? Wk[(size_t)(k0 + kk) * GG + g] : 0.0f;
        }
        #pragma unroll
        for (int i = threadIdx.x; i < 1024; i += 256) {
            int kk = i >> 6, cc = i & 63;
            Bs[kk][cc] = g_xT[((size_t)t * FF + k0 + kk) * BB + n0 + cc];
        }
        __syncthreads();
        #pragma unroll
        for (int kk = 0; kk < 16; kk++) {
            float av[4], bv[4];
            #pragma unroll
            for (int m = 0; m < 4; m++) av[m] = As[ty * 4 + m][kk];
            #pragma unroll
            for (int n = 0; n < 4; n++) bv[n] = Bs[kk][tx * 4 + n];
            #pragma unroll
            for (int m = 0; m < 4; m++)
                #pragma unroll
                for (int n = 0; n < 4; n++) acc[m][n] += av[m] * bv[n];
        }
        __syncthreads();
    }
    #pragma unroll
    for (int m = 0; m < 4; m++) {
        int g = m0 + ty * 4 + m;
        if (g < GG) {
            float bv = g_bias[g];
            #pragma unroll
            for (int n = 0; n < 4; n++)
                g_xkT[((size_t)t * GG + g) * BB + n0 + tx * 4 + n] = acc[m][n] + bv;
        }
    }
}

// ---------- THE persistent recurrence ----------
extern __shared__ float dsm[];
__global__ __launch_bounds__(256, 1) void stage_persistent(const float* __restrict__ Wr)
{
    float* wr_s = dsm;
    float* a_s  = dsm + 384 * WRS;
    float* xo_s = a_s + 3 * 256 * AST;
    const int tid = threadIdx.x, blk = blockIdx.x, j0 = blk * JC;
    const int w = tid >> 5, lane = tid & 31, gq = lane >> 2, tg = lane & 3;
    const int m0 = w * 32, lgrp = j0 >> 7;

    unsigned* wru = (unsigned*)wr_s;
    for (int idx = tid; idx < 384 * NPAD; idx += 256) {
        int k = idx / NPAD, n = idx - k * NPAD;
        float v = (n < NCOL) ? Wr[(size_t)k * GG + gcol(n, j0)] : 0.0f;
        wru[k * WRS + n] = f2tf32(v);
    }
    __syncthreads();

    float c_reg[JC];
    #pragma unroll
    for (int jj = 0; jj < JC; jj++) c_reg[jj] = 0.0f;
    unsigned gen = 0;
    const int c4 = (tid & 7) * 4, r0b = tid >> 3;

    for (int t = 0; t < TT; t++) {
        const float* hc = g_h2[t & 1];
        float*       hn = g_h2[(t + 1) & 1];

        float xk_reg[NCOL];
        {
            const float* base = g_xkT + (size_t)t * GG * BB + tid;
            #pragma unroll
            for (int c = 0; c < NCOL; c++) xk_reg[c] = __ldcs(base + (size_t)gcol(c, j0) * BB);
        }

        float acc[2][NT][4];
        #pragma unroll
        for (int mt = 0; mt < 2; mt++)
            #pragma unroll
            for (int nt = 0; nt < NT; nt++)
                #pragma unroll
                for (int q = 0; q < 4; q++) acc[mt][nt][q] = 0.0f;

        auto prefetch = [&](int kc, int s) {
            float* dst = a_s + s * (256 * AST);
            const float* src = hc + kc * KC;
            #pragma unroll
            for (int i = 0; i < 8; i++) {
                int r = r0b + 32 * i;
                cp16(dst + r * AST + c4, src + (size_t)r * HH + c4);
            }
            asm volatile("cp.async.commit_group;");
        };
        prefetch(0, 0);
        prefetch(1, 1);

        for (int kc = 0; kc < NCHUNK; kc++) {
            if (kc < NCHUNK - 1) asm volatile("cp.async.wait_group 1;");
            else                 asm volatile("cp.async.wait_group 0;");
            __syncthreads();
            if (kc + 2 < NCHUNK) prefetch(kc + 2, (kc + 2) % 3);
            const float* sb = a_s + (kc % 3) * (256 * AST);
            #pragma unroll
            for (int k8 = 0; k8 < 4; k8++) {
                const int kb = k8 * 8;
                unsigned bf[NT][2];
                const int krow = (kc * KC + kb + tg) * WRS;
                #pragma unroll
                for (int nt = 0; nt < NT; nt++) {
                    bf[nt][0] = wru[krow + nt * 8 + gq];
                    bf[nt][1] = wru[krow + 4 * WRS + nt * 8 + gq];
                }
                #pragma unroll
                for (int mt = 0; mt < 2; mt++) {
                    unsigned af[4];
                    const float* ap = sb + (m0 + mt * 16 + gq) * AST + kb + tg;
                    af[0] = __float_as_uint(ap[0]);
                    af[1] = __float_as_uint(ap[8 * AST]);
                    af[2] = __float_as_uint(ap[4]);
                    af[3] = __float_as_uint(ap[8 * AST + 4]);
                    #pragma unroll
                    for (int nt = 0; nt < NT; nt++) mma8(acc[mt][nt], af, bf[nt]);
                }
            }
        }

        #pragma unroll
        for (int mt = 0; mt < 2; mt++) {
            int r = m0 + mt * 16 + gq;
            #pragma unroll
            for (int nt = 0; nt < NT; nt++) {
                int cb = nt * 8 + 2 * tg;
                xo_s[r * XOS + cb]           = acc[mt][nt][0];
                xo_s[r * XOS + cb + 1]       = acc[mt][nt][1];
                xo_s[(r + 8) * XOS + cb]     = acc[mt][nt][2];
                xo_s[(r + 8) * XOS + cb + 1] = acc[mt][nt][3];
            }
        }
        __syncthreads();

        {
            float xv[NCOL];
            #pragma unroll
            for (int c = 0; c < NCOL; c++) xv[c] = xo_s[tid * XOS + c] + xk_reg[c];
            float a0 = xv[0], a1 = xv[1], a2 = xv[2];
            float m = fmaxf(a0, fmaxf(a1, a2));
            float e0 = expf(a0 - m), e1 = expf(a1 - m), e2 = expf(a2 - m);
            float s = e0 + e1 + e2;
            float p0 = e0 / s, p1 = e1 / s;
            float f0 = p0, f1 = p0 + p1;
            float b0 = xv[3], b1 = xv[4], b2 = xv[5];
            m = fmaxf(b0, fmaxf(b1, b2));
            e0 = expf(b0 - m); e1 = expf(b1 - m); e2 = expf(b2 - m);
            s = e0 + e1 + e2;
            float q1 = e1 / s, q2 = e2 / s;
            float fm = (lgrp == 0) ? f0 : ((lgrp == 1) ? f1 : 1.0f);
            float im = (lgrp == 0) ? 1.0f : ((lgrp == 1) ? q1 + q2 : q2);
            float ov = fm * im;
            float cd = 1.0f - (f0 + f1 + 1.0f) * (1.0f / 3.0f);
            const bool hist = (t >= TT - KKW);
            const int slot = t % KKW;
            #pragma unroll
            for (int jj = 0; jj < JC; jj++) {
                int j = j0 + jj;
                float fg = sigmoidf(xv[6 + jj]);
                float ig = sigmoidf(xv[6 + JC + jj]);
                float og = sigmoidf(xv[6 + 2 * JC + jj]);
                float ci = tanhf(xv[6 + 3 * JC + jj]);
                float cn = c_reg[jj] * (ov * fg + fm - ov) + ci * (ov * ig + im - ov);
                c_reg[jj] = cn;
                float hv = og * tanhf(cn);
                hn[tid * HH + j] = hv;
                if (hist) g_hist_h[slot * BB * HH + tid * HH + j] = hv;
            }
            if (hist && j0 == 0) g_hist_d[slot * BB + tid] = cd;
        }

        gen++;
        __syncthreads();
        if (tid == 0) {
            __threadfence();
            atomicAdd(&g_arrive, 1u);
            unsigned tgt = gen * NBLK, v;
            do {
                asm volatile("ld.global.acquire.gpu.u32 %0, [%1];" : "=r"(v) : "l"(&g_arrive));
                if (v < tgt) __nanosleep(64);
            } while (v < tgt);
        }
        __syncthreads();
    }
}

// ---------- final head ----------
__global__ void dis_kernel() {
    int b = threadIdx.x;
    if (b >= BB) return;
    float cum = 0.0f, v[KKW];
    #pragma unroll
    for (int k = 0; k < KKW; k++) {
        cum += g_hist_d[((TT - KKW + k) % KKW) * BB + b];
        v[k] = cum;
    }
    float m = v[0];
    #pragma unroll
    for (int k = 1; k < KKW; k++) m = fmaxf(m, v[k]);
    float s = 0.0f;
    #pragma unroll
    for (int k = 0; k < KKW; k++) { v[k] = expf(v[k] - m); s += v[k]; }
    float inv = 1.0f / s;
    #pragma unroll
    for (int k = 0; k < KKW; k++) g_dis[b * KKW + k] = v[k] * inv;
}
__global__ void wh_kernel() {
    int idx = blockIdx.x * blockDim.x + threadIdx.x;
    if (idx >= BB * HH) return;
    int b = idx / HH;
    float acc = 0.0f;
    #pragma unroll
    for (int k = 0; k < KKW; k++) {
        float v = g_hist_h[((TT - KKW + k) % KKW) * BB * HH + idx] * g_dis[b * KKW + k];
        g_wh[k * BB * HH + idx] = v;
        acc += v;
    }
    g_M[idx] = acc * (1.0f / KKW);
}
__global__ __launch_bounds__(256) void conv_kernel(const float* __restrict__ bc) {
    __shared__ float Asm[16][65];
    __shared__ float Bsm[16][64];
    const int tx = threadIdx.x & 15, ty = threadIdx.x >> 4;
    const int b0 = blockIdx.y * 64, o0 = blockIdx.x * 64;
    float acc[4][4] = {};
    for (int kk0 = 0; kk0 < KKW * HH; kk0 += 16) {
        #pragma unroll
        for (int x2 = threadIdx.x; x2 < 1024; x2 += 256) {
            int bb = x2 >> 4, kk = x2 & 15;
            int kkidx = kk0 + kk, k = kkidx / HH, i = kkidx - k * HH;
            Asm[kk][bb] = g_wh[k * BB * HH + (b0 + bb) * HH + i];
        }
        #pragma unroll
        for (int x2 = threadIdx.x; x2 < 1024; x2 += 256) {
            int kk = x2 >> 6, oo = x2 & 63;
            Bsm[kk][oo] = g_wct[(size_t)(kk0 + kk) * HH + o0 + oo];
        }
        __syncthreads();
        #pragma unroll
        for (int kk = 0; kk < 16; kk++) {
            float av[4], bv[4];
            #pragma unroll
            for (int m = 0; m < 4; m++) av[m] = Asm[kk][ty * 4 + m];
            #pragma unroll
            for (int n = 0; n < 4; n++) bv[n] = Bsm[kk][tx * 4 + n];
            #pragma unroll
            for (int m = 0; m < 4; m++)
                #pragma unroll
                for (int n = 0; n < 4; n++) acc[m][n] += av[m] * bv[n];
        }
        __syncthreads();
    }
    #pragma unroll
    for (int m = 0; m < 4; m++)
        #pragma unroll
        for (int n = 0; n < 4; n++)
            g_conv[(b0 + ty * 4 + m) * HH + o0 + tx * 4 + n] = acc[m][n] + bc[o0 + tx * 4 + n];
}
__global__ void p_kernel(const float* __restrict__ Ws, const float* __restrict__ bs) {
    int b = blockIdx.x, s2 = threadIdx.x;
    float acc = bs[s2];
    for (int i = 0; i < HH; i++) acc += g_M[b * HH + i] * Ws[i * SS + s2];
    g_P[b * SS + s2] = fmaxf(acc, 0.0f);
}
__global__ void theme_kernel(const float* __restrict__ Wrs, const float* __restrict__ brs) {
    int b = blockIdx.x, o = threadIdx.x;
    float acc = brs[o];
    #pragma unroll 8
    for (int s2 = 0; s2 < SS; s2++) acc += g_P[b * SS + s2] * Wrs[s2 * HH + o];
    g_theme[b * HH + o] = sigmoidf(acc);
}
__global__ void out_kernel(const float* __restrict__ Wo, const float* __restrict__ bo,
                           float* __restrict__ out) {
    int b = blockIdx.x;
    __shared__ float red[128];
    float acc = 0.0f;
    for (int i = threadIdx.x; i < HH; i += 128) {
        float rnn = g_theme[b * HH + i] * g_conv[b * HH + i] + g_h2[0][b * HH + i];
        acc += rnn * Wo[i];
    }
    red[threadIdx.x] = acc;
    __syncthreads();
    for (int s = 64; s > 0; s >>= 1) {
        if (threadIdx.x < s) red[threadIdx.x] += red[threadIdx.x + s];
        __syncthreads();
    }
    if (threadIdx.x == 0) out[b] = sigmoidf(red[0] + bo[0]);
}

// ---------- host ----------
extern "C" void kernel_launch(void* const* d_in, const int* in_sizes, int n_in,
                              void* d_out, int out_size)
{
    (void)in_sizes; (void)n_in; (void)out_size;
    const float* x   = (const float*)d_in[0];
    const float* Wk  = (const float*)d_in[1];
    const float* bk  = (const float*)d_in[2];
    const float* Wr  = (const float*)d_in[3];
    const float* br  = (const float*)d_in[4];
    const float* Ws  = (const float*)d_in[5];
    const float* bs  = (const float*)d_in[6];
    const float* Wrs = (const float*)d_in[7];
    const float* brs = (const float*)d_in[8];
    const float* Wc  = (const float*)d_in[9];
    const float* bc  = (const float*)d_in[10];
    const float* Wo  = (const float*)d_in[11];
    const float* bo  = (const float*)d_in[12];

    cudaFuncSetAttribute(stage_persistent, cudaFuncAttributeMaxDynamicSharedMemorySize, SMEM_BYTES);

    bias_kernel<<<(GG + 255) / 256, 256>>>(Wk, bk, Wr, br);
    init_state_kernel<<<(BB * HH + 255) / 256, 256>>>();
    wct_kernel<<<(KKW * HH * HH + 255) / 256, 256>>>(Wc);
    xT_kernel<<<dim3(FF / 32, BB / 32, TT), dim3(32, 8)>>>(x);
    sgemmT<<<dim3(BB / 64, (GG + 63) / 64, TT), 256>>>(Wk);

    stage_persistent<<<NBLK, 256, SMEM_BYTES>>>(Wr);

    dis_kernel<<<1, 256>>>();
    wh_kernel<<<(BB * HH + 255) / 256, 256>>>();
    conv_kernel<<<dim3(HH / 64, BB / 64), 256>>>(bc);
    p_kernel<<<BB, SS>>>(Ws, bs);
    theme_kernel<<<BB, HH>>>(Wrs, brs);
    out_kernel<<<BB, 128>>>(Wo, bo, (float*)d_out);
}

// round 4
// speedup vs baseline: 3.4305x; 1.6744x over previous
#include <cuda_runtime.h>
#include <cuda_bf16.h>
#include <math.h>

#define TT 256
#define BB 256
#define FF 128
#define HH 384
#define LL 3
#define KKW 10
#define GG 1542
#define SS 64

#define NBLK 96
#define JC 4
#define NCOL 22
#define NPAD 24
#define NT 3
#define WRS 40          // wru row stride (uint32), k2-rows
#define AST 36          // a_s row stride (uint32)
#define XOS 25
#define KC 64           // k per chunk
#define KC2 32          // packed uint32 per chunk
#define NCHUNK 6
#define SMEM_BYTES ((192*WRS + 3*256*AST + 0)*4 + 256*XOS*4)

// precompute mma kernel smem
#define PAST 68         // A_s row stride uint32
#define PBST 132        // B_s row stride uint32
#define GP 1664         // padded G (13*128)
#define PSMEM ((128*PAST + 64*PBST)*4)

static __device__ float    g_xkT[(size_t)TT * GG * BB];   // [t][g][b] fp32
static __device__ unsigned g_xp[(size_t)TT * (FF/2) * BB]; // packed bf16 pairs [t][k2][b]
static __device__ unsigned g_wkp[GP * (FF/2)];             // [g][k2] packed pairs
static __device__ unsigned g_h2u[2][BB * (HH/2)];          // packed bf16 h
static __device__ float g_hist_h[KKW * BB * HH];
static __device__ float g_hist_d[KKW * BB];
static __device__ float g_dis[BB * KKW];
static __device__ float g_wh[KKW * BB * HH];
static __device__ float g_M[BB * HH];
static __device__ float g_P[BB * SS];
static __device__ float g_theme[BB * HH];
static __device__ float g_conv[BB * HH];
static __device__ float g_bias[GG];
static __device__ float g_wct[KKW * HH * HH];
static __device__ unsigned g_arrive;

__device__ __forceinline__ float sigmoidf(float x) { return 1.0f / (1.0f + expf(-x)); }
__device__ __forceinline__ int gcol(int n, int j0) {
    return (n < 6) ? n : 6 + ((n - 6) >> 2) * HH + j0 + ((n - 6) & 3);
}
__device__ __forceinline__ unsigned packbf(float lo, float hi) {
    __nv_bfloat162 p = __floats2bfloat162_rn(lo, hi);
    return *(unsigned*)&p;
}
__device__ __forceinline__ void mma16(float* d, const unsigned* a, const unsigned* b) {
    asm volatile("mma.sync.aligned.m16n8k16.row.col.f32.bf16.bf16.f32 "
                 "{%0,%1,%2,%3}, {%4,%5,%6,%7}, {%8,%9}, {%0,%1,%2,%3};"
                 : "+f"(d[0]), "+f"(d[1]), "+f"(d[2]), "+f"(d[3])
                 : "r"(a[0]), "r"(a[1]), "r"(a[2]), "r"(a[3]), "r"(b[0]), "r"(b[1]));
}
__device__ __forceinline__ void cp16(void* s, const void* g) {
    unsigned sa = (unsigned)__cvta_generic_to_shared(s);
    asm volatile("cp.async.cg.shared.global [%0], [%1], 16;" :: "r"(sa), "l"(g));
}

// ---------- setup ----------
__global__ void bias_kernel(const float* __restrict__ Wk, const float* __restrict__ bk,
                            const float* __restrict__ Wr, const float* __restrict__ br) {
    int j = blockIdx.x * blockDim.x + threadIdx.x;
    if (j < GG) g_bias[j] = bk[j] + br[j] + Wk[FF * GG + j] + Wr[HH * GG + j];
}
__global__ void init_state_kernel() {
    int i = blockIdx.x * blockDim.x + threadIdx.x;
    if (i < BB * (HH/2)) g_h2u[0][i] = 0u;
    if (i == 0) g_arrive = 0u;
}
__global__ void wct_kernel(const float* __restrict__ Wc) {
    int idx = blockIdx.x * blockDim.x + threadIdx.x;
    if (idx >= KKW * HH * HH) return;
    int kkidx = idx / HH, o = idx - kkidx * HH;
    int k = kkidx / HH, i = kkidx - k * HH;
    g_wct[idx] = Wc[(o * HH + i) * KKW + k];
}
// pack x into [t][k2][b] bf16 pairs
__global__ void xp_kernel(const float* __restrict__ x) {
    __shared__ float tile[32][33];   // [b][f]
    int t = blockIdx.z, f0 = blockIdx.x * 32, b0 = blockIdx.y * 32;
    int tx = threadIdx.x, ty = threadIdx.y;
    #pragma unroll
    for (int i = 0; i < 4; i++)
        tile[ty + 8 * i][tx] = x[((size_t)t * BB + b0 + ty + 8 * i) * FF + f0 + tx];
    __syncthreads();
    #pragma unroll
    for (int i = 0; i < 2; i++) {
        int k2l = ty + 8 * i;   // 0..15
        unsigned v = packbf(tile[tx][2 * k2l], tile[tx][2 * k2l + 1]);
        g_xp[((size_t)t * (FF/2) + f0/2 + k2l) * BB + b0 + tx] = v;
    }
}
// pack Wk^T into [g][k2]
__global__ void wkp_kernel(const float* __restrict__ Wk) {
    int idx = blockIdx.x * blockDim.x + threadIdx.x;   // k2*GP + g
    if (idx >= (FF/2) * GP) return;
    int k2 = idx / GP, g = idx - k2 * GP;
    unsigned v = 0u;
    if (g < GG) v = packbf(Wk[(size_t)(2*k2) * GG + g], Wk[(size_t)(2*k2+1) * GG + g]);
    g_wkp[g * (FF/2) + k2] = v;
}

// ---------- precompute GEMM (bf16 mma): xkT[t][g][b] = WkT[g,:]@x[t,b,:] + bias ----------
extern __shared__ unsigned psm[];
__global__ __launch_bounds__(256, 2) void xk_mma() {
    unsigned* A_s = psm;                   // [128][PAST]
    unsigned* B_s = psm + 128 * PAST;      // [64][PBST]
    const int t = blockIdx.z, gt = blockIdx.y, bt = blockIdx.x;
    const int tid = threadIdx.x, w = tid >> 5, lane = tid & 31;
    const int gq = lane >> 2, tg = lane & 3;
    const int m0w = (w >> 2) * 64, n0w = (w & 3) * 32;

    for (int e = tid; e < 128 * 16; e += 256) {
        int r = e >> 4, seg = e & 15;
        cp16(A_s + r * PAST + seg * 4, g_wkp + (size_t)(gt * 128 + r) * 64 + seg * 4);
    }
    for (int e = tid; e < 64 * 32; e += 256) {
        int r = e >> 5, seg = e & 31;
        cp16(B_s + r * PBST + seg * 4,
             g_xp + ((size_t)t * 64 + r) * BB + bt * 128 + seg * 4);
    }
    asm volatile("cp.async.commit_group;");
    asm volatile("cp.async.wait_group 0;");
    __syncthreads();

    float acc[4][4][4];
    #pragma unroll
    for (int a = 0; a < 4; a++)
        #pragma unroll
        for (int b = 0; b < 4; b++)
            #pragma unroll
            for (int q = 0; q < 4; q++) acc[a][b][q] = 0.0f;

    #pragma unroll
    for (int k16 = 0; k16 < 8; k16++) {
        const int kb2 = k16 * 8;
        unsigned af[4][4];
        #pragma unroll
        for (int mt = 0; mt < 4; mt++) {
            const unsigned* ap = A_s + (m0w + mt * 16 + gq) * PAST + kb2 + tg;
            af[mt][0] = ap[0]; af[mt][1] = ap[8 * PAST];
            af[mt][2] = ap[4]; af[mt][3] = ap[8 * PAST + 4];
        }
        #pragma unroll
        for (int nt = 0; nt < 4; nt++) {
            const unsigned* bp = B_s + (kb2 + tg) * PBST + n0w + nt * 8 + gq;
            unsigned bf[2] = { bp[0], bp[4 * PBST] };
            #pragma unroll
            for (int mt = 0; mt < 4; mt++) mma16(acc[mt][nt], af[mt], bf);
        }
    }
    #pragma unroll
    for (int mt = 0; mt < 4; mt++) {
        #pragma unroll
        for (int rr = 0; rr < 2; rr++) {
            int g = gt * 128 + m0w + mt * 16 + gq + rr * 8;
            if (g >= GG) continue;
            float bv = g_bias[g];
            float* out = g_xkT + ((size_t)t * GG + g) * BB + bt * 128 + n0w;
            #pragma unroll
            for (int nt = 0; nt < 4; nt++) {
                out[nt * 8 + 2 * tg]     = acc[mt][nt][rr * 2]     + bv;
                out[nt * 8 + 2 * tg + 1] = acc[mt][nt][rr * 2 + 1] + bv;
            }
        }
    }
}

// ---------- persistent recurrence (bf16 mma) ----------
extern __shared__ unsigned dsm[];
__global__ __launch_bounds__(256, 1) void stage_persistent(const float* __restrict__ Wr)
{
    unsigned* wru = dsm;                        // [192][WRS]
    unsigned* a_s = dsm + 192 * WRS;            // 3 x [256][AST]
    float* xo_s   = (float*)(a_s + 3 * 256 * AST);
    const int tid = threadIdx.x, blk = blockIdx.x, j0 = blk * JC;
    const int w = tid >> 5, lane = tid & 31, gq = lane >> 2, tg = lane & 3;
    const int m0 = w * 32, lgrp = j0 >> 7;

    for (int idx = tid; idx < 192 * NPAD; idx += 256) {
        int k2 = idx / NPAD, n = idx - k2 * NPAD;
        unsigned v = 0u;
        if (n < NCOL) {
            int c = gcol(n, j0);
            v = packbf(Wr[(size_t)(2*k2) * GG + c], Wr[(size_t)(2*k2+1) * GG + c]);
        }
        wru[k2 * WRS + n] = v;
    }
    __syncthreads();

    float c_reg[JC];
    #pragma unroll
    for (int jj = 0; jj < JC; jj++) c_reg[jj] = 0.0f;
    unsigned gen = 0;
    const int c4 = (tid & 7) * 4, r0b = tid >> 3;

    for (int t = 0; t < TT; t++) {
        const unsigned* hc = g_h2u[t & 1];
        unsigned*       hn = g_h2u[(t + 1) & 1];

        float xk_reg[NCOL];
        {
            const float* base = g_xkT + (size_t)t * GG * BB + tid;
            #pragma unroll
            for (int c = 0; c < NCOL; c++) xk_reg[c] = __ldcs(base + (size_t)gcol(c, j0) * BB);
        }

        float acc[2][NT][4];
        #pragma unroll
        for (int mt = 0; mt < 2; mt++)
            #pragma unroll
            for (int nt = 0; nt < NT; nt++)
                #pragma unroll
                for (int q = 0; q < 4; q++) acc[mt][nt][q] = 0.0f;

        auto prefetch = [&](int kc, int s) {
            unsigned* dst = a_s + s * (256 * AST);
            const unsigned* src = hc + kc * KC2;
            #pragma unroll
            for (int i = 0; i < 8; i++) {
                int r = r0b + 32 * i;
                cp16(dst + r * AST + c4, src + (size_t)r * (HH/2) + c4);
            }
            asm volatile("cp.async.commit_group;");
        };
        prefetch(0, 0);
        prefetch(1, 1);

        for (int kc = 0; kc < NCHUNK; kc++) {
            if (kc < NCHUNK - 1) asm volatile("cp.async.wait_group 1;");
            else                 asm volatile("cp.async.wait_group 0;");
            __syncthreads();
            if (kc + 2 < NCHUNK) prefetch(kc + 2, (kc + 2) % 3);
            const unsigned* sb = a_s + (kc % 3) * (256 * AST);
            #pragma unroll
            for (int k16 = 0; k16 < 4; k16++) {
                const int kb2 = k16 * 8;
                const int krow = (kc * KC2 + kb2 + tg) * WRS;
                unsigned bf[NT][2];
                #pragma unroll
                for (int nt = 0; nt < NT; nt++) {
                    bf[nt][0] = wru[krow + nt * 8 + gq];
                    bf[nt][1] = wru[krow + 4 * WRS + nt * 8 + gq];
                }
                #pragma unroll
                for (int mt = 0; mt < 2; mt++) {
                    const unsigned* ap = sb + (m0 + mt * 16 + gq) * AST + kb2 + tg;
                    unsigned af[4] = { ap[0], ap[8 * AST], ap[4], ap[8 * AST + 4] };
                    #pragma unroll
                    for (int nt = 0; nt < NT; nt++) mma16(acc[mt][nt], af, bf[nt]);
                }
            }
        }

        #pragma unroll
        for (int mt = 0; mt < 2; mt++) {
            int r = m0 + mt * 16 + gq;
            #pragma unroll
            for (int nt = 0; nt < NT; nt++) {
                int cb = nt * 8 + 2 * tg;
                xo_s[r * XOS + cb]           = acc[mt][nt][0];
                xo_s[r * XOS + cb + 1]       = acc[mt][nt][1];
                xo_s[(r + 8) * XOS + cb]     = acc[mt][nt][2];
                xo_s[(r + 8) * XOS + cb + 1] = acc[mt][nt][3];
            }
        }
        __syncthreads();

        {
            float xv[NCOL];
            #pragma unroll
            for (int c = 0; c < NCOL; c++) xv[c] = xo_s[tid * XOS + c] + xk_reg[c];
            float a0 = xv[0], a1 = xv[1], a2 = xv[2];
            float m = fmaxf(a0, fmaxf(a1, a2));
            float e0 = expf(a0 - m), e1 = expf(a1 - m), e2 = expf(a2 - m);
            float s = e0 + e1 + e2;
            float p0 = e0 / s, p1 = e1 / s;
            float f0 = p0, f1 = p0 + p1;
            float b0 = xv[3], b1 = xv[4], b2 = xv[5];
            m = fmaxf(b0, fmaxf(b1, b2));
            e0 = expf(b0 - m); e1 = expf(b1 - m); e2 = expf(b2 - m);
            s = e0 + e1 + e2;
            float q1 = e1 / s, q2 = e2 / s;
            float fm = (lgrp == 0) ? f0 : ((lgrp == 1) ? f1 : 1.0f);
            float im = (lgrp == 0) ? 1.0f : ((lgrp == 1) ? q1 + q2 : q2);
            float ov = fm * im;
            float cd = 1.0f - (f0 + f1 + 1.0f) * (1.0f / 3.0f);
            const bool hist = (t >= TT - KKW);
            const int slot = t % KKW;
            float hv[JC];
            #pragma unroll
            for (int jj = 0; jj < JC; jj++) {
                float fg = sigmoidf(xv[6 + jj]);
                float ig = sigmoidf(xv[6 + JC + jj]);
                float og = sigmoidf(xv[6 + 2 * JC + jj]);
                float ci = tanhf(xv[6 + 3 * JC + jj]);
                float cn = c_reg[jj] * (ov * fg + fm - ov) + ci * (ov * ig + im - ov);
                c_reg[jj] = cn;
                hv[jj] = og * tanhf(cn);
                if (hist) g_hist_h[slot * BB * HH + tid * HH + j0 + jj] = hv[jj];
            }
            hn[tid * (HH/2) + j0/2]     = packbf(hv[0], hv[1]);
            hn[tid * (HH/2) + j0/2 + 1] = packbf(hv[2], hv[3]);
            if (hist && j0 == 0) g_hist_d[slot * BB + tid] = cd;
        }

        gen++;
        __syncthreads();
        if (tid == 0) {
            __threadfence();
            atomicAdd(&g_arrive, 1u);
            unsigned tgt = gen * NBLK, v;
            do {
                asm volatile("ld.global.acquire.gpu.u32 %0, [%1];" : "=r"(v) : "l"(&g_arrive));
                if (v < tgt) __nanosleep(64);
            } while (v < tgt);
        }
        __syncthreads();
    }
}

// ---------- final head ----------
__global__ void dis_kernel() {
    int b = threadIdx.x;
    if (b >= BB) return;
    float cum = 0.0f, v[KKW];
    #pragma unroll
    for (int k = 0; k < KKW; k++) {
        cum += g_hist_d[((TT - KKW + k) % KKW) * BB + b];
        v[k] = cum;
    }
    float m = v[0];
    #pragma unroll
    for (int k = 1; k < KKW; k++) m = fmaxf(m, v[k]);
    float s = 0.0f;
    #pragma unroll
    for (int k = 0; k < KKW; k++) { v[k] = expf(v[k] - m); s += v[k]; }
    float inv = 1.0f / s;
    #pragma unroll
    for (int k = 0; k < KKW; k++) g_dis[b * KKW + k] = v[k] * inv;
}
__global__ void wh_kernel() {
    int idx = blockIdx.x * blockDim.x + threadIdx.x;
    if (idx >= BB * HH) return;
    int b = idx / HH;
    float acc = 0.0f;
    #pragma unroll
    for (int k = 0; k < KKW; k++) {
        float v = g_hist_h[((TT - KKW + k) % KKW) * BB * HH + idx] * g_dis[b * KKW + k];
        g_wh[k * BB * HH + idx] = v;
        acc += v;
    }
    g_M[idx] = acc * (1.0f / KKW);
}
__global__ __launch_bounds__(256) void conv_kernel(const float* __restrict__ bc) {
    __shared__ float Asm[16][65];
    __shared__ float Bsm[16][64];
    const int tx = threadIdx.x & 15, ty = threadIdx.x >> 4;
    const int b0 = blockIdx.y * 64, o0 = blockIdx.x * 64;
    float acc[4][4] = {};
    for (int kk0 = 0; kk0 < KKW * HH; kk0 += 16) {
        #pragma unroll
        for (int x2 = threadIdx.x; x2 < 1024; x2 += 256) {
            int bb = x2 >> 4, kk = x2 & 15;
            int kkidx = kk0 + kk, k = kkidx / HH, i = kkidx - k * HH;
            Asm[kk][bb] = g_wh[k * BB * HH + (b0 + bb) * HH + i];
        }
        #pragma unroll
        for (int x2 = threadIdx.x; x2 < 1024; x2 += 256) {
            int kk = x2 >> 6, oo = x2 & 63;
            Bsm[kk][oo] = g_wct[(size_t)(kk0 + kk) * HH + o0 + oo];
        }
        __syncthreads();
        #pragma unroll
        for (int kk = 0; kk < 16; kk++) {
            float av[4], bv[4];
            #pragma unroll
            for (int m = 0; m < 4; m++) av[m] = Asm[kk][ty * 4 + m];
            #pragma unroll
            for (int n = 0; n < 4; n++) bv[n] = Bsm[kk][tx * 4 + n];
            #pragma unroll
            for (int m = 0; m < 4; m++)
                #pragma unroll
                for (int n = 0; n < 4; n++) acc[m][n] += av[m] * bv[n];
        }
        __syncthreads();
    }
    #pragma unroll
    for (int m = 0; m < 4; m++)
        #pragma unroll
        for (int n = 0; n < 4; n++)
            g_conv[(b0 + ty * 4 + m) * HH + o0 + tx * 4 + n] = acc[m][n] + bc[o0 + tx * 4 + n];
}
__global__ void p_kernel(const float* __restrict__ Ws, const float* __restrict__ bs) {
    int b = blockIdx.x, s2 = threadIdx.x;
    float acc = bs[s2];
    for (int i = 0; i < HH; i++) acc += g_M[b * HH + i] * Ws[i * SS + s2];
    g_P[b * SS + s2] = fmaxf(acc, 0.0f);
}
__global__ void theme_kernel(const float* __restrict__ Wrs, const float* __restrict__ brs) {
    int b = blockIdx.x, o = threadIdx.x;
    float acc = brs[o];
    #pragma unroll 8
    for (int s2 = 0; s2 < SS; s2++) acc += g_P[b * SS + s2] * Wrs[s2 * HH + o];
    g_theme[b * HH + o] = sigmoidf(acc);
}
__global__ void out_kernel(const float* __restrict__ Wo, const float* __restrict__ bo,
                           float* __restrict__ out) {
    int b = blockIdx.x;
    __shared__ float red[128];
    float acc = 0.0f;
    for (int i2 = threadIdx.x; i2 < HH/2; i2 += 128) {
        unsigned p = g_h2u[0][b * (HH/2) + i2];
        __nv_bfloat162 h2 = *(__nv_bfloat162*)&p;
        int i = 2 * i2;
        float r0 = g_theme[b * HH + i]     * g_conv[b * HH + i]     + __bfloat162float(h2.x);
        float r1 = g_theme[b * HH + i + 1] * g_conv[b * HH + i + 1] + __bfloat162float(h2.y);
        acc += r0 * Wo[i] + r1 * Wo[i + 1];
    }
    red[threadIdx.x] = acc;
    __syncthreads();
    for (int s = 64; s > 0; s >>= 1) {
        if (threadIdx.x < s) red[threadIdx.x] += red[threadIdx.x + s];
        __syncthreads();
    }
    if (threadIdx.x == 0) out[b] = sigmoidf(red[0] + bo[0]);
}

// ---------- host ----------
extern "C" void kernel_launch(void* const* d_in, const int* in_sizes, int n_in,
                              void* d_out, int out_size)
{
    (void)in_sizes; (void)n_in; (void)out_size;
    const float* x   = (const float*)d_in[0];
    const float* Wk  = (const float*)d_in[1];
    const float* bk  = (const float*)d_in[2];
    const float* Wr  = (const float*)d_in[3];
    const float* br  = (const float*)d_in[4];
    const float* Ws  = (const float*)d_in[5];
    const float* bs  = (const float*)d_in[6];
    const float* Wrs = (const float*)d_in[7];
    const float* brs = (const float*)d_in[8];
    const float* Wc  = (const float*)d_in[9];
    const float* bc  = (const float*)d_in[10];
    const float* Wo  = (const float*)d_in[11];
    const float* bo  = (const float*)d_in[12];

    cudaFuncSetAttribute(stage_persistent, cudaFuncAttributeMaxDynamicSharedMemorySize, SMEM_BYTES);
    cudaFuncSetAttribute(xk_mma, cudaFuncAttributeMaxDynamicSharedMemorySize, PSMEM);

    bias_kernel<<<(GG + 255) / 256, 256>>>(Wk, bk, Wr, br);
    init_state_kernel<<<(BB * HH + 255) / 256, 256>>>();
    wct_kernel<<<(KKW * HH * HH + 255) / 256, 256>>>(Wc);
    xp_kernel<<<dim3(FF / 32, BB / 32, TT), dim3(32, 8)>>>(x);
    wkp_kernel<<<((FF/2) * GP + 255) / 256, 256>>>(Wk);
    xk_mma<<<dim3(2, 13, TT), 256, PSMEM>>>();

    stage_persistent<<<NBLK, 256, SMEM_BYTES>>>(Wr);

    dis_kernel<<<1, 256>>>();
    wh_kernel<<<(BB * HH + 255) / 256, 256>>>();
    conv_kernel<<<dim3(HH / 64, BB / 64), 256>>>(bc);
    p_kernel<<<BB, SS>>>(Ws, bs);
    theme_kernel<<<BB, HH>>>(Wrs, brs);
    out_kernel<<<BB, 128>>>(Wo, bo, (float*)d_out);
}

// round 6
// speedup vs baseline: 3.5476x; 1.0341x over previous
#include <cuda_runtime.h>
#include <cuda_bf16.h>
#include <math.h>
#include <stdint.h>

#define TT 256
#define BB 256
#define FF 128
#define HH 384
#define LL 3
#define KKW 10
#define GG 1542
#define SS 64

#define NBLK 128        // 2 batch-halves x 64 col-slices
#define JC 6
#define NCOL 30         // 6 softmax + 4*JC
#define NPAD 32
#define NT 4
#define WRS 40          // wru row stride (u32) per k2-row
#define AST 36          // staged-A row stride (u32)
#define XOS 33
#define KC2 32          // packed u32 per chunk (=64 k)
#define NCHUNK 6
#define SMEM_BYTES ((192*WRS + 3*128*AST + 128*XOS)*4)

// precompute mma kernel smem
#define PAST 68
#define PBST 132
#define GP 1664
#define PSMEM ((128*PAST + 64*PBST)*4)

static __device__ unsigned g_xkb[(size_t)TT * GG * BB / 2]; // bf16 [t][g][b]
static __device__ unsigned g_xp[(size_t)TT * (FF/2) * BB];
static __device__ unsigned g_wkp[GP * (FF/2)];
static __device__ unsigned g_h2u[2][BB * (HH/2)];           // packed bf16 h
static __device__ float g_hist_h[KKW * BB * HH];
static __device__ float g_hist_d[KKW * BB];
static __device__ float g_dis[BB * KKW];
static __device__ float g_wh[KKW * BB * HH];
static __device__ float g_M[BB * HH];
static __device__ float g_P[BB * SS];
static __device__ float g_theme[BB * HH];
static __device__ float g_conv[BB * HH];
static __device__ float g_bias[GG];
static __device__ float g_wct[KKW * HH * HH];
static __device__ unsigned g_arrive;

__device__ __forceinline__ float sigmoidf(float x) { return 1.0f / (1.0f + expf(-x)); }
__device__ __forceinline__ int gcol6(int n, int j0) {
    return (n < 6) ? n : 6 + ((n - 6) / 6) * HH + j0 + ((n - 6) % 6);
}
__device__ __forceinline__ unsigned packbf(float lo, float hi) {
    __nv_bfloat162 p = __floats2bfloat162_rn(lo, hi);
    return *(unsigned*)&p;
}
__device__ __forceinline__ void mma16(float* d, const unsigned* a, const unsigned* b) {
    asm volatile("mma.sync.aligned.m16n8k16.row.col.f32.bf16.bf16.f32 "
                 "{%0,%1,%2,%3}, {%4,%5,%6,%7}, {%8,%9}, {%0,%1,%2,%3};"
                 : "+f"(d[0]), "+f"(d[1]), "+f"(d[2]), "+f"(d[3])
                 : "r"(a[0]), "r"(a[1]), "r"(a[2]), "r"(a[3]), "r"(b[0]), "r"(b[1]));
}
__device__ __forceinline__ void cp16(void* s, const void* g) {
    unsigned sa = (unsigned)__cvta_generic_to_shared(s);
    asm volatile("cp.async.cg.shared.global [%0], [%1], 16;" :: "r"(sa), "l"(g));
}

// ---------- setup ----------
__global__ void bias_kernel(const float* __restrict__ Wk, const float* __restrict__ bk,
                            const float* __restrict__ Wr, const float* __restrict__ br) {
    int j = blockIdx.x * blockDim.x + threadIdx.x;
    if (j < GG) g_bias[j] = bk[j] + br[j] + Wk[FF * GG + j] + Wr[HH * GG + j];
}
__global__ void init_state_kernel() {
    int i = blockIdx.x * blockDim.x + threadIdx.x;
    if (i < BB * (HH/2)) g_h2u[0][i] = 0u;
    if (i == 0) g_arrive = 0u;
}
__global__ void wct_kernel(const float* __restrict__ Wc) {
    int idx = blockIdx.x * blockDim.x + threadIdx.x;
    if (idx >= KKW * HH * HH) return;
    int kkidx = idx / HH, o = idx - kkidx * HH;
    int k = kkidx / HH, i = kkidx - k * HH;
    g_wct[idx] = Wc[(o * HH + i) * KKW + k];
}
__global__ void xp_kernel(const float* __restrict__ x) {
    __shared__ float tile[32][33];
    int t = blockIdx.z, f0 = blockIdx.x * 32, b0 = blockIdx.y * 32;
    int tx = threadIdx.x, ty = threadIdx.y;
    #pragma unroll
    for (int i = 0; i < 4; i++)
        tile[ty + 8 * i][tx] = x[((size_t)t * BB + b0 + ty + 8 * i) * FF + f0 + tx];
    __syncthreads();
    #pragma unroll
    for (int i = 0; i < 2; i++) {
        int k2l = ty + 8 * i;
        unsigned v = packbf(tile[tx][2 * k2l], tile[tx][2 * k2l + 1]);
        g_xp[((size_t)t * (FF/2) + f0/2 + k2l) * BB + b0 + tx] = v;
    }
}
__global__ void wkp_kernel(const float* __restrict__ Wk) {
    int idx = blockIdx.x * blockDim.x + threadIdx.x;
    if (idx >= (FF/2) * GP) return;
    int k2 = idx / GP, g = idx - k2 * GP;
    unsigned v = 0u;
    if (g < GG) v = packbf(Wk[(size_t)(2*k2) * GG + g], Wk[(size_t)(2*k2+1) * GG + g]);
    g_wkp[g * (FF/2) + k2] = v;
}

// ---------- precompute GEMM (bf16 mma): xkb[t][g][b] = WkT[g,:]@x[t,b,:] + bias ----------
extern __shared__ unsigned psm[];
__global__ __launch_bounds__(256, 2) void xk_mma() {
    unsigned* A_s = psm;
    unsigned* B_s = psm + 128 * PAST;
    const int t = blockIdx.z, gt = blockIdx.y, bt = blockIdx.x;
    const int tid = threadIdx.x, w = tid >> 5, lane = tid & 31;
    const int gq = lane >> 2, tg = lane & 3;
    const int m0w = (w >> 2) * 64, n0w = (w & 3) * 32;

    for (int e = tid; e < 128 * 16; e += 256) {
        int r = e >> 4, seg = e & 15;
        cp16(A_s + r * PAST + seg * 4, g_wkp + (size_t)(gt * 128 + r) * 64 + seg * 4);
    }
    for (int e = tid; e < 64 * 32; e += 256) {
        int r = e >> 5, seg = e & 31;
        cp16(B_s + r * PBST + seg * 4,
             g_xp + ((size_t)t * 64 + r) * BB + bt * 128 + seg * 4);
    }
    asm volatile("cp.async.commit_group;");
    asm volatile("cp.async.wait_group 0;");
    __syncthreads();

    float acc[4][4][4];
    #pragma unroll
    for (int a = 0; a < 4; a++)
        #pragma unroll
        for (int b = 0; b < 4; b++)
            #pragma unroll
            for (int q = 0; q < 4; q++) acc[a][b][q] = 0.0f;

    #pragma unroll
    for (int k16 = 0; k16 < 8; k16++) {
        const int kb2 = k16 * 8;
        unsigned af[4][4];
        #pragma unroll
        for (int mt = 0; mt < 4; mt++) {
            const unsigned* ap = A_s + (m0w + mt * 16 + gq) * PAST + kb2 + tg;
            af[mt][0] = ap[0]; af[mt][1] = ap[8 * PAST];
            af[mt][2] = ap[4]; af[mt][3] = ap[8 * PAST + 4];
        }
        #pragma unroll
        for (int nt = 0; nt < 4; nt++) {
            const unsigned* bp = B_s + (kb2 + tg) * PBST + n0w + nt * 8 + gq;
            unsigned bf[2] = { bp[0], bp[4 * PBST] };
            #pragma unroll
            for (int mt = 0; mt < 4; mt++) mma16(acc[mt][nt], af[mt], bf);
        }
    }
    #pragma unroll
    for (int mt = 0; mt < 4; mt++) {
        #pragma unroll
        for (int rr = 0; rr < 2; rr++) {
            int g = gt * 128 + m0w + mt * 16 + gq + rr * 8;
            if (g >= GG) continue;
            float bv = g_bias[g];
            unsigned* out = g_xkb + (((size_t)t * GG + g) * BB + bt * 128 + n0w) / 2;
            #pragma unroll
            for (int nt = 0; nt < 4; nt++)
                out[nt * 4 + tg] = packbf(acc[mt][nt][rr * 2] + bv, acc[mt][nt][rr * 2 + 1] + bv);
        }
    }
}

// ---------- persistent recurrence (bf16 mma, M=128 per block) ----------
extern __shared__ unsigned dsm[];
__global__ __launch_bounds__(256, 1) void stage_persistent(const float* __restrict__ Wr)
{
    unsigned* wru = dsm;                         // [192][WRS]
    unsigned* a_s = dsm + 192 * WRS;             // 3 x [128][AST]
    float* xo_s   = (float*)(a_s + 3 * 128 * AST);
    const int tid = threadIdx.x, blk = blockIdx.x;
    const int half = blk & 1, slice = blk >> 1;
    const int b0 = half * 128, j0 = slice * JC;
    const int w = tid >> 5, lane = tid & 31, gq = lane >> 2, tg = lane & 3;
    const int m0 = w * 16;

    for (int idx = tid; idx < 192 * NPAD; idx += 256) {
        int k2 = idx >> 5, n = idx & 31;
        unsigned v = 0u;
        if (n < NCOL) {
            int c = gcol6(n, j0);
            v = packbf(Wr[(size_t)(2*k2) * GG + c], Wr[(size_t)(2*k2+1) * GG + c]);
        }
        wru[k2 * WRS + n] = v;
    }
    __syncthreads();

    float c_reg[JC];
    #pragma unroll
    for (int jj = 0; jj < JC; jj++) c_reg[jj] = 0.0f;
    unsigned gen = 0;
    const int c4 = (tid & 7) * 4, r0b = tid >> 3;

    for (int t = 0; t < TT; t++) {
        const unsigned* hc = g_h2u[t & 1] + (size_t)b0 * (HH/2);
        unsigned*       hn = g_h2u[(t + 1) & 1];

        float xk_reg[NCOL];
        if (tid < 128) {
            const __nv_bfloat16* base =
                (const __nv_bfloat16*)g_xkb + (size_t)t * GG * BB + b0 + tid;
            #pragma unroll
            for (int c = 0; c < NCOL; c++)
                xk_reg[c] = __bfloat162float(base[(size_t)gcol6(c, j0) * BB]);
        }

        float acc[NT][4];
        #pragma unroll
        for (int nt = 0; nt < NT; nt++)
            #pragma unroll
            for (int q = 0; q < 4; q++) acc[nt][q] = 0.0f;

        auto prefetch = [&](int kc, int s) {
            unsigned* dst = a_s + s * (128 * AST);
            const unsigned* src = hc + kc * KC2;
            #pragma unroll
            for (int i = 0; i < 4; i++) {
                int r = r0b + 32 * i;
                cp16(dst + r * AST + c4, src + (size_t)r * (HH/2) + c4);
            }
            asm volatile("cp.async.commit_group;");
        };
        prefetch(0, 0);
        prefetch(1, 1);

        for (int kc = 0; kc < NCHUNK; kc++) {
            if (kc < NCHUNK - 1) asm volatile("cp.async.wait_group 1;");
            else                 asm volatile("cp.async.wait_group 0;");
            __syncthreads();
            if (kc + 2 < NCHUNK) prefetch(kc + 2, (kc + 2) % 3);
            const unsigned* sb = a_s + (kc % 3) * (128 * AST);
            #pragma unroll
            for (int k16 = 0; k16 < 4; k16++) {
                const int kb2 = k16 * 8;
                const int krow = (kc * KC2 + kb2 + tg) * WRS;
                const unsigned* ap = sb + (m0 + gq) * AST + kb2 + tg;
                unsigned af[4] = { ap[0], ap[8 * AST], ap[4], ap[8 * AST + 4] };
                #pragma unroll
                for (int nt = 0; nt < NT; nt++) {
                    unsigned bf[2] = { wru[krow + nt * 8 + gq], wru[krow + 4 * WRS + nt * 8 + gq] };
                    mma16(acc[nt], af, bf);
                }
            }
        }

        {
            int r = m0 + gq;
            #pragma unroll
            for (int nt = 0; nt < NT; nt++) {
                int cb = nt * 8 + 2 * tg;
                xo_s[r * XOS + cb]           = acc[nt][0];
                xo_s[r * XOS + cb + 1]       = acc[nt][1];
                xo_s[(r + 8) * XOS + cb]     = acc[nt][2];
                xo_s[(r + 8) * XOS + cb + 1] = acc[nt][3];
            }
        }
        __syncthreads();

        if (tid < 128) {
            float xv[NCOL];
            #pragma unroll
            for (int c = 0; c < NCOL; c++) xv[c] = xo_s[tid * XOS + c] + xk_reg[c];
            float a0 = xv[0], a1 = xv[1], a2 = xv[2];
            float m = fmaxf(a0, fmaxf(a1, a2));
            float e0 = __expf(a0 - m), e1 = __expf(a1 - m), e2 = __expf(a2 - m);
            float s = e0 + e1 + e2;
            float p0 = e0 / s, p1 = e1 / s;
            float f0 = p0, f1 = p0 + p1;
            float b1v = xv[4], b0v = xv[3], b2v = xv[5];
            m = fmaxf(b0v, fmaxf(b1v, b2v));
            e0 = __expf(b0v - m); e1 = __expf(b1v - m); e2 = __expf(b2v - m);
            s = e0 + e1 + e2;
            float q1 = e1 / s, q2 = e2 / s;
            float i1 = q1 + q2, i2 = q2;
            float cd = 1.0f - (f0 + f1 + 1.0f) * (1.0f / 3.0f);
            const bool hist = (t >= TT - KKW);
            const int slot = t % KKW;
            float hv[JC];
            #pragma unroll
            for (int jj = 0; jj < JC; jj++) {
                int lg = (j0 + jj) >> 7;
                float fm = (lg == 0) ? f0 : ((lg == 1) ? f1 : 1.0f);
                float im = (lg == 0) ? 1.0f : ((lg == 1) ? i1 : i2);
                float ov = fm * im;
                float fg = sigmoidf(xv[6 + jj]);
                float ig = sigmoidf(xv[6 + JC + jj]);
                float og = sigmoidf(xv[6 + 2 * JC + jj]);
                float ci = tanhf(xv[6 + 3 * JC + jj]);
                float cn = c_reg[jj] * (ov * fg + fm - ov) + ci * (ov * ig + im - ov);
                c_reg[jj] = cn;
                hv[jj] = og * tanhf(cn);
                if (hist) g_hist_h[slot * BB * HH + (b0 + tid) * HH + j0 + jj] = hv[jj];
            }
            unsigned* hp = hn + (size_t)(b0 + tid) * (HH/2) + (j0 >> 1);
            hp[0] = packbf(hv[0], hv[1]);
            hp[1] = packbf(hv[2], hv[3]);
            hp[2] = packbf(hv[4], hv[5]);
            if (hist && slice == 0) g_hist_d[slot * BB + b0 + tid] = cd;
        }

        gen++;
        __syncthreads();
        if (tid == 0) {
            __threadfence();
            atomicAdd(&g_arrive, 1u);
            unsigned tgt = gen * NBLK, v;
            do {
                asm volatile("ld.global.acquire.gpu.u32 %0, [%1];" : "=r"(v) : "l"(&g_arrive));
                if (v < tgt) __nanosleep(64);
            } while (v < tgt);
        }
        __syncthreads();
    }
}

// ---------- final head ----------
__global__ void dis_kernel() {
    int b = threadIdx.x;
    if (b >= BB) return;
    float cum = 0.0f, v[KKW];
    #pragma unroll
    for (int k = 0; k < KKW; k++) {
        cum += g_hist_d[((TT - KKW + k) % KKW) * BB + b];
        v[k] = cum;
    }
    float m = v[0];
    #pragma unroll
    for (int k = 1; k < KKW; k++) m = fmaxf(m, v[k]);
    float s = 0.0f;
    #pragma unroll
    for (int k = 0; k < KKW; k++) { v[k] = expf(v[k] - m); s += v[k]; }
    float inv = 1.0f / s;
    #pragma unroll
    for (int k = 0; k < KKW; k++) g_dis[b * KKW + k] = v[k] * inv;
}
__global__ void wh_kernel() {
    int idx = blockIdx.x * blockDim.x + threadIdx.x;
    if (idx >= BB * HH) return;
    int b = idx / HH;
    float acc = 0.0f;
    #pragma unroll
    for (int k = 0; k < KKW; k++) {
        float v = g_hist_h[((TT - KKW + k) % KKW) * BB * HH + idx] * g_dis[b * KKW + k];
        g_wh[k * BB * HH + idx] = v;
        acc += v;
    }
    g_M[idx] = acc * (1.0f / KKW);
}
__global__ __launch_bounds__(256) void conv_kernel(const float* __restrict__ bc) {
    __shared__ float Asm[16][65];
    __shared__ float Bsm[16][64];
    const int tx = threadIdx.x & 15, ty = threadIdx.x >> 4;
    const int b0 = blockIdx.y * 64, o0 = blockIdx.x * 64;
    float acc[4][4] = {};
    for (int kk0 = 0; kk0 < KKW * HH; kk0 += 16) {
        #pragma unroll
        for (int x2 = threadIdx.x; x2 < 1024; x2 += 256) {
            int bb = x2 >> 4, kk = x2 & 15;
            int kkidx = kk0 + kk, k = kkidx / HH, i = kkidx - k * HH;
            Asm[kk][bb] = g_wh[k * BB * HH + (b0 + bb) * HH + i];
        }
        #pragma unroll
        for (int x2 = threadIdx.x; x2 < 1024; x2 += 256) {
            int kk = x2 >> 6, oo = x2 & 63;
            Bsm[kk][oo] = g_wct[(size_t)(kk0 + kk) * HH + o0 + oo];
        }
        __syncthreads();
        #pragma unroll
        for (int kk = 0; kk < 16; kk++) {
            float av[4], bv[4];
            #pragma unroll
            for (int m = 0; m < 4; m++) av[m] = Asm[kk][ty * 4 + m];
            #pragma unroll
            for (int n = 0; n < 4; n++) bv[n] = Bsm[kk][tx * 4 + n];
            #pragma unroll
            for (int m = 0; m < 4; m++)
                #pragma unroll
                for (int n = 0; n < 4; n++) acc[m][n] += av[m] * bv[n];
        }
        __syncthreads();
    }
    #pragma unroll
    for (int m = 0; m < 4; m++)
        #pragma unroll
        for (int n = 0; n < 4; n++)
            g_conv[(b0 + ty * 4 + m) * HH + o0 + tx * 4 + n] = acc[m][n] + bc[o0 + tx * 4 + n];
}
__global__ void p_kernel(const float* __restrict__ Ws, const float* __restrict__ bs) {
    int b = blockIdx.x, s2 = threadIdx.x;
    float acc = bs[s2];
    for (int i = 0; i < HH; i++) acc += g_M[b * HH + i] * Ws[i * SS + s2];
    g_P[b * SS + s2] = fmaxf(acc, 0.0f);
}
__global__ void theme_kernel(const float* __restrict__ Wrs, const float* __restrict__ brs) {
    int b = blockIdx.x, o = threadIdx.x;
    float acc = brs[o];
    #pragma unroll 8
    for (int s2 = 0; s2 < SS; s2++) acc += g_P[b * SS + s2] * Wrs[s2 * HH + o];
    g_theme[b * HH + o] = sigmoidf(acc);
}
__global__ void out_kernel(const float* __restrict__ Wo, const float* __restrict__ bo,
                           float* __restrict__ out) {
    int b = blockIdx.x;
    __shared__ float red[128];
    const float* hfin = g_hist_h + ((TT - 1) % KKW) * BB * HH;
    float acc = 0.0f;
    for (int i = threadIdx.x; i < HH; i += 128) {
        float rnn = g_theme[b * HH + i] * g_conv[b * HH + i] + hfin[b * HH + i];
        acc += rnn * Wo[i];
    }
    red[threadIdx.x] = acc;
    __syncthreads();
    for (int s = 64; s > 0; s >>= 1) {
        if (threadIdx.x < s) red[threadIdx.x] += red[threadIdx.x + s];
        __syncthreads();
    }
    if (threadIdx.x == 0) out[b] = sigmoidf(red[0] + bo[0]);
}

// ---------- host ----------
extern "C" void kernel_launch(void* const* d_in, const int* in_sizes, int n_in,
                              void* d_out, int out_size)
{
    (void)in_sizes; (void)n_in; (void)out_size;
    const float* x   = (const float*)d_in[0];
    const float* Wk  = (const float*)d_in[1];
    const float* bk  = (const float*)d_in[2];
    const float* Wr  = (const float*)d_in[3];
    const float* br  = (const float*)d_in[4];
    const float* Ws  = (const float*)d_in[5];
    const float* bs  = (const float*)d_in[6];
    const float* Wrs = (const float*)d_in[7];
    const float* brs = (const float*)d_in[8];
    const float* Wc  = (const float*)d_in[9];
    const float* bc  = (const float*)d_in[10];
    const float* Wo  = (const float*)d_in[11];
    const float* bo  = (const float*)d_in[12];

    cudaFuncSetAttribute(stage_persistent, cudaFuncAttributeMaxDynamicSharedMemorySize, SMEM_BYTES);
    cudaFuncSetAttribute(xk_mma, cudaFuncAttributeMaxDynamicSharedMemorySize, PSMEM);

    bias_kernel<<<(GG + 255) / 256, 256>>>(Wk, bk, Wr, br);
    init_state_kernel<<<(BB * HH + 255) / 256, 256>>>();
    wct_kernel<<<(KKW * HH * HH + 255) / 256, 256>>>(Wc);
    xp_kernel<<<dim3(FF / 32, BB / 32, TT), dim3(32, 8)>>>(x);
    wkp_kernel<<<((FF/2) * GP + 255) / 256, 256>>>(Wk);
    xk_mma<<<dim3(2, 13, TT), 256, PSMEM>>>();

    stage_persistent<<<NBLK, 256, SMEM_BYTES>>>(Wr);

    dis_kernel<<<1, 256>>>();
    wh_kernel<<<(BB * HH + 255) / 256, 256>>>();
    conv_kernel<<<dim3(HH / 64, BB / 64), 256>>>(bc);
    p_kernel<<<BB, SS>>>(Ws, bs);
    theme_kernel<<<BB, HH>>>(Wrs, brs);
    out_kernel<<<BB, 128>>>(Wo, bo, (float*)d_out);
}

// round 7
// speedup vs baseline: 5.1141x; 1.4416x over previous
#include <cuda_runtime.h>
#include <cuda_bf16.h>
#include <math.h>
#include <stdint.h>

#define TT 256
#define BB 256
#define FF 128
#define HH 384
#define LL 3
#define KKW 10
#define GG 1542
#define SS 64

#define NBLK 128        // 2 batch-halves x 64 col-slices
#define JC 6
#define NCOL 30
#define NPAD 32
#define NT 4
#define WRS 40          // wru row stride (u32)
#define AST 68          // chunk-buffer row stride (u32): 64 data + 4 pad
#define XOS 33
#define SMEM_BYTES ((192*WRS + 3*128*AST + 128*XOS)*4)

// precompute mma kernel smem
#define PAST 68
#define PBST 132
#define GP 1664
#define PSMEM ((128*PAST + 64*PBST)*4)

static __device__ unsigned g_xkb[(size_t)TT * GG * BB / 2]; // bf16 [t][g][b]
static __device__ unsigned g_xp[(size_t)TT * (FF/2) * BB];
static __device__ unsigned g_wkp[GP * (FF/2)];
static __device__ unsigned g_h2u[2][BB * (HH/2)];           // packed bf16 h
static __device__ float g_hist_h[KKW * BB * HH];
static __device__ float g_hist_d[KKW * BB];
static __device__ float g_dis[BB * KKW];
static __device__ float g_wh[KKW * BB * HH];
static __device__ float g_M[BB * HH];
static __device__ float g_P[BB * SS];
static __device__ float g_theme[BB * HH];
static __device__ float g_conv[BB * HH];
static __device__ float g_bias[GG];
static __device__ float g_wct[KKW * HH * HH];
static __device__ unsigned g_arrive;

__device__ __forceinline__ float sigmoidf(float x) { return 1.0f / (1.0f + expf(-x)); }
__device__ __forceinline__ float tanha(float x) {
    float y; asm("tanh.approx.f32 %0, %1;" : "=f"(y) : "f"(x)); return y;
}
__device__ __forceinline__ float siga(float x) { return fmaf(0.5f, tanha(0.5f * x), 0.5f); }
__device__ __forceinline__ int gcol6(int n, int j0) {
    return (n < 6) ? n : 6 + ((n - 6) / 6) * HH + j0 + ((n - 6) % 6);
}
__device__ __forceinline__ unsigned packbf(float lo, float hi) {
    __nv_bfloat162 p = __floats2bfloat162_rn(lo, hi);
    return *(unsigned*)&p;
}
__device__ __forceinline__ void mma16(float* d, const unsigned* a, const unsigned* b) {
    asm volatile("mma.sync.aligned.m16n8k16.row.col.f32.bf16.bf16.f32 "
                 "{%0,%1,%2,%3}, {%4,%5,%6,%7}, {%8,%9}, {%0,%1,%2,%3};"
                 : "+f"(d[0]), "+f"(d[1]), "+f"(d[2]), "+f"(d[3])
                 : "r"(a[0]), "r"(a[1]), "r"(a[2]), "r"(a[3]), "r"(b[0]), "r"(b[1]));
}
__device__ __forceinline__ void cp16(void* s, const void* g) {
    unsigned sa = (unsigned)__cvta_generic_to_shared(s);
    asm volatile("cp.async.cg.shared.global [%0], [%1], 16;" :: "r"(sa), "l"(g));
}

// ---------- setup ----------
__global__ void bias_kernel(const float* __restrict__ Wk, const float* __restrict__ bk,
                            const float* __restrict__ Wr, const float* __restrict__ br) {
    int j = blockIdx.x * blockDim.x + threadIdx.x;
    if (j < GG) g_bias[j] = bk[j] + br[j] + Wk[FF * GG + j] + Wr[HH * GG + j];
}
__global__ void init_state_kernel() {
    int i = blockIdx.x * blockDim.x + threadIdx.x;
    if (i < BB * (HH/2)) g_h2u[0][i] = 0u;
    if (i == 0) g_arrive = 0u;
}
__global__ void wct_kernel(const float* __restrict__ Wc) {
    int idx = blockIdx.x * blockDim.x + threadIdx.x;
    if (idx >= KKW * HH * HH) return;
    int kkidx = idx / HH, o = idx - kkidx * HH;
    int k = kkidx / HH, i = kkidx - k * HH;
    g_wct[idx] = Wc[(o * HH + i) * KKW + k];
}
__global__ void xp_kernel(const float* __restrict__ x) {
    __shared__ float tile[32][33];
    int t = blockIdx.z, f0 = blockIdx.x * 32, b0 = blockIdx.y * 32;
    int tx = threadIdx.x, ty = threadIdx.y;
    #pragma unroll
    for (int i = 0; i < 4; i++)
        tile[ty + 8 * i][tx] = x[((size_t)t * BB + b0 + ty + 8 * i) * FF + f0 + tx];
    __syncthreads();
    #pragma unroll
    for (int i = 0; i < 2; i++) {
        int k2l = ty + 8 * i;
        unsigned v = packbf(tile[tx][2 * k2l], tile[tx][2 * k2l + 1]);
        g_xp[((size_t)t * (FF/2) + f0/2 + k2l) * BB + b0 + tx] = v;
    }
}
__global__ void wkp_kernel(const float* __restrict__ Wk) {
    int idx = blockIdx.x * blockDim.x + threadIdx.x;
    if (idx >= (FF/2) * GP) return;
    int k2 = idx / GP, g = idx - k2 * GP;
    unsigned v = 0u;
    if (g < GG) v = packbf(Wk[(size_t)(2*k2) * GG + g], Wk[(size_t)(2*k2+1) * GG + g]);
    g_wkp[g * (FF/2) + k2] = v;
}

// ---------- precompute GEMM ----------
extern __shared__ unsigned psm[];
__global__ __launch_bounds__(256, 2) void xk_mma() {
    unsigned* A_s = psm;
    unsigned* B_s = psm + 128 * PAST;
    const int t = blockIdx.z, gt = blockIdx.y, bt = blockIdx.x;
    const int tid = threadIdx.x, w = tid >> 5, lane = tid & 31;
    const int gq = lane >> 2, tg = lane & 3;
    const int m0w = (w >> 2) * 64, n0w = (w & 3) * 32;

    for (int e = tid; e < 128 * 16; e += 256) {
        int r = e >> 4, seg = e & 15;
        cp16(A_s + r * PAST + seg * 4, g_wkp + (size_t)(gt * 128 + r) * 64 + seg * 4);
    }
    for (int e = tid; e < 64 * 32; e += 256) {
        int r = e >> 5, seg = e & 31;
        cp16(B_s + r * PBST + seg * 4,
             g_xp + ((size_t)t * 64 + r) * BB + bt * 128 + seg * 4);
    }
    asm volatile("cp.async.commit_group;");
    asm volatile("cp.async.wait_group 0;");
    __syncthreads();

    float acc[4][4][4];
    #pragma unroll
    for (int a = 0; a < 4; a++)
        #pragma unroll
        for (int b = 0; b < 4; b++)
            #pragma unroll
            for (int q = 0; q < 4; q++) acc[a][b][q] = 0.0f;

    #pragma unroll
    for (int k16 = 0; k16 < 8; k16++) {
        const int kb2 = k16 * 8;
        unsigned af[4][4];
        #pragma unroll
        for (int mt = 0; mt < 4; mt++) {
            const unsigned* ap = A_s + (m0w + mt * 16 + gq) * PAST + kb2 + tg;
            af[mt][0] = ap[0]; af[mt][1] = ap[8 * PAST];
            af[mt][2] = ap[4]; af[mt][3] = ap[8 * PAST + 4];
        }
        #pragma unroll
        for (int nt = 0; nt < 4; nt++) {
            const unsigned* bp = B_s + (kb2 + tg) * PBST + n0w + nt * 8 + gq;
            unsigned bf[2] = { bp[0], bp[4 * PBST] };
            #pragma unroll
            for (int mt = 0; mt < 4; mt++) mma16(acc[mt][nt], af[mt], bf);
        }
    }
    #pragma unroll
    for (int mt = 0; mt < 4; mt++) {
        #pragma unroll
        for (int rr = 0; rr < 2; rr++) {
            int g = gt * 128 + m0w + mt * 16 + gq + rr * 8;
            if (g >= GG) continue;
            float bv = g_bias[g];
            unsigned* out = g_xkb + (((size_t)t * GG + g) * BB + bt * 128 + n0w) / 2;
            #pragma unroll
            for (int nt = 0; nt < 4; nt++)
                out[nt * 4 + tg] = packbf(acc[mt][nt][rr * 2] + bv, acc[mt][nt][rr * 2 + 1] + bv);
        }
    }
}

// ---------- persistent recurrence: warp-autonomous pipeline ----------
extern __shared__ unsigned dsm[];
__global__ __launch_bounds__(256, 1) void stage_persistent(const float* __restrict__ Wr)
{
    unsigned* wru = dsm;                         // [192][WRS]
    unsigned* a_s = dsm + 192 * WRS;             // 3 chunk buffers [128][AST]
    float* xo_s   = (float*)(a_s + 3 * 128 * AST);
    const int tid = threadIdx.x, blk = blockIdx.x;
    const int half = blk & 1, slice = blk >> 1;
    const int b0 = half * 128, j0 = slice * JC;
    const int w = tid >> 5, lane = tid & 31, gq = lane >> 2, tg = lane & 3;
    const int m0 = w * 16;

    for (int idx = tid; idx < 192 * NPAD; idx += 256) {
        int k2 = idx >> 5, n = idx & 31;
        unsigned v = 0u;
        if (n < NCOL) {
            int c = gcol6(n, j0);
            v = packbf(Wr[(size_t)(2*k2) * GG + c], Wr[(size_t)(2*k2+1) * GG + c]);
        }
        wru[k2 * WRS + n] = v;
    }
    __syncthreads();

    float c_reg[JC];
    #pragma unroll
    for (int jj = 0; jj < JC; jj++) c_reg[jj] = 0.0f;

    // xk prefetch for t=0
    float xk_reg[NCOL];
    if (tid < 128) {
        const __nv_bfloat16* base = (const __nv_bfloat16*)g_xkb + b0 + tid;
        #pragma unroll
        for (int c = 0; c < NCOL; c++)
            xk_reg[c] = __bfloat162float(base[(size_t)gcol6(c, j0) * BB]);
    }

    for (int t = 0; t < TT; t++) {
        // ---- wait for all h(t) slices (skip trivially at t=0: target 0) ----
        if (tid == 0) {
            unsigned tgt = (unsigned)t * NBLK, v;
            do {
                asm volatile("ld.global.acquire.gpu.u32 %0, [%1];" : "=r"(v) : "l"(&g_arrive));
            } while (v < tgt);
        }
        __syncthreads();

        const unsigned* hc = g_h2u[t & 1] + (size_t)b0 * (HH/2);
        unsigned*       hn = g_h2u[(t + 1) & 1];

        // ---- per-warp: stage own 16 A-rows in 3 chunk-groups, mma without any barrier ----
        #pragma unroll
        for (int c = 0; c < 3; c++) {
            unsigned* dst = a_s + c * (128 * AST);
            #pragma unroll
            for (int i = 0; i < 8; i++) {
                int seg = lane + 32 * i;          // 0..255
                int r = m0 + (seg >> 4);
                int so = (seg & 15) * 4;
                cp16(dst + r * AST + so, hc + (size_t)r * (HH/2) + c * 64 + so);
            }
            asm volatile("cp.async.commit_group;");
        }

        float acc[NT][4];
        #pragma unroll
        for (int nt = 0; nt < NT; nt++)
            #pragma unroll
            for (int q = 0; q < 4; q++) acc[nt][q] = 0.0f;

        #pragma unroll
        for (int c = 0; c < 3; c++) {
            if (c == 0)      asm volatile("cp.async.wait_group 2;");
            else if (c == 1) asm volatile("cp.async.wait_group 1;");
            else             asm volatile("cp.async.wait_group 0;");
            const unsigned* sb = a_s + c * (128 * AST);
            #pragma unroll
            for (int s = 0; s < 8; s++) {
                const int kb2 = s * 8;
                const int krow = (c * 64 + kb2 + tg) * WRS;
                const unsigned* ap = sb + (m0 + gq) * AST + kb2 + tg;
                unsigned af[4] = { ap[0], ap[8 * AST], ap[4], ap[8 * AST + 4] };
                #pragma unroll
                for (int nt = 0; nt < NT; nt++) {
                    unsigned bf[2] = { wru[krow + nt * 8 + gq], wru[krow + 4 * WRS + nt * 8 + gq] };
                    mma16(acc[nt], af, bf);
                }
            }
        }

        {
            int r = m0 + gq;
            #pragma unroll
            for (int nt = 0; nt < NT; nt++) {
                int cb = nt * 8 + 2 * tg;
                xo_s[r * XOS + cb]           = acc[nt][0];
                xo_s[r * XOS + cb + 1]       = acc[nt][1];
                xo_s[(r + 8) * XOS + cb]     = acc[nt][2];
                xo_s[(r + 8) * XOS + cb + 1] = acc[nt][3];
            }
        }
        __syncthreads();

        // ---- gates (tid<128; MUFU tanh) ----
        if (tid < 128) {
            float xv[NCOL];
            #pragma unroll
            for (int c = 0; c < NCOL; c++) xv[c] = xo_s[tid * XOS + c] + xk_reg[c];
            float a0 = xv[0], a1 = xv[1], a2 = xv[2];
            float m = fmaxf(a0, fmaxf(a1, a2));
            float e0 = __expf(a0 - m), e1 = __expf(a1 - m), e2 = __expf(a2 - m);
            float rs = __fdividef(1.0f, e0 + e1 + e2);
            float f0 = e0 * rs, f1 = (e0 + e1) * rs;
            float b0v = xv[3], b1v = xv[4], b2v = xv[5];
            m = fmaxf(b0v, fmaxf(b1v, b2v));
            e0 = __expf(b0v - m); e1 = __expf(b1v - m); e2 = __expf(b2v - m);
            rs = __fdividef(1.0f, e0 + e1 + e2);
            float i1 = (e1 + e2) * rs, i2 = e2 * rs;
            float cd = 1.0f - (f0 + f1 + 1.0f) * (1.0f / 3.0f);
            const bool hist = (t >= TT - KKW);
            const int slot = t % KKW;
            float hv[JC];
            #pragma unroll
            for (int jj = 0; jj < JC; jj++) {
                int lg = (j0 + jj) >> 7;
                float fm = (lg == 0) ? f0 : ((lg == 1) ? f1 : 1.0f);
                float im = (lg == 0) ? 1.0f : ((lg == 1) ? i1 : i2);
                float ov = fm * im;
                float fg = siga(xv[6 + jj]);
                float ig = siga(xv[6 + JC + jj]);
                float og = siga(xv[6 + 2 * JC + jj]);
                float ci = tanha(xv[6 + 3 * JC + jj]);
                float cn = c_reg[jj] * (ov * fg + fm - ov) + ci * (ov * ig + im - ov);
                c_reg[jj] = cn;
                hv[jj] = og * tanha(cn);
                if (hist) g_hist_h[slot * BB * HH + (b0 + tid) * HH + j0 + jj] = hv[jj];
            }
            unsigned* hp = hn + (size_t)(b0 + tid) * (HH/2) + (j0 >> 1);
            hp[0] = packbf(hv[0], hv[1]);
            hp[1] = packbf(hv[2], hv[3]);
            hp[2] = packbf(hv[4], hv[5]);
            if (hist && slice == 0) g_hist_d[slot * BB + b0 + tid] = cd;
        }

        // ---- arrive (h published), then prefetch next xk during others' wait ----
        __syncthreads();
        if (tid == 0) {
            __threadfence();
            atomicAdd(&g_arrive, 1u);
        }
        if (tid < 128) {
            int tn = (t + 1 < TT) ? t + 1 : t;
            const __nv_bfloat16* base =
                (const __nv_bfloat16*)g_xkb + (size_t)tn * GG * BB + b0 + tid;
            #pragma unroll
            for (int c = 0; c < NCOL; c++)
                xk_reg[c] = __bfloat162float(base[(size_t)gcol6(c, j0) * BB]);
        }
    }
}

// ---------- final head ----------
__global__ void dis_kernel() {
    int b = threadIdx.x;
    if (b >= BB) return;
    float cum = 0.0f, v[KKW];
    #pragma unroll
    for (int k = 0; k < KKW; k++) {
        cum += g_hist_d[((TT - KKW + k) % KKW) * BB + b];
        v[k] = cum;
    }
    float m = v[0];
    #pragma unroll
    for (int k = 1; k < KKW; k++) m = fmaxf(m, v[k]);
    float s = 0.0f;
    #pragma unroll
    for (int k = 0; k < KKW; k++) { v[k] = expf(v[k] - m); s += v[k]; }
    float inv = 1.0f / s;
    #pragma unroll
    for (int k = 0; k < KKW; k++) g_dis[b * KKW + k] = v[k] * inv;
}
__global__ void wh_kernel() {
    int idx = blockIdx.x * blockDim.x + threadIdx.x;
    if (idx >= BB * HH) return;
    int b = idx / HH;
    float acc = 0.0f;
    #pragma unroll
    for (int k = 0; k < KKW; k++) {
        float v = g_hist_h[((TT - KKW + k) % KKW) * BB * HH + idx] * g_dis[b * KKW + k];
        g_wh[k * BB * HH + idx] = v;
        acc += v;
    }
    g_M[idx] = acc * (1.0f / KKW);
}
__global__ __launch_bounds__(256) void conv_kernel(const float* __restrict__ bc) {
    __shared__ float Asm[16][65];
    __shared__ float Bsm[16][64];
    const int tx = threadIdx.x & 15, ty = threadIdx.x >> 4;
    const int b0 = blockIdx.y * 64, o0 = blockIdx.x * 64;
    float acc[4][4] = {};
    for (int kk0 = 0; kk0 < KKW * HH; kk0 += 16) {
        #pragma unroll
        for (int x2 = threadIdx.x; x2 < 1024; x2 += 256) {
            int bb = x2 >> 4, kk = x2 & 15;
            int kkidx = kk0 + kk, k = kkidx / HH, i = kkidx - k * HH;
            Asm[kk][bb] = g_wh[k * BB * HH + (b0 + bb) * HH + i];
        }
        #pragma unroll
        for (int x2 = threadIdx.x; x2 < 1024; x2 += 256) {
            int kk = x2 >> 6, oo = x2 & 63;
            Bsm[kk][oo] = g_wct[(size_t)(kk0 + kk) * HH + o0 + oo];
        }
        __syncthreads();
        #pragma unroll
        for (int kk = 0; kk < 16; kk++) {
            float av[4], bv[4];
            #pragma unroll
            for (int m = 0; m < 4; m++) av[m] = Asm[kk][ty * 4 + m];
            #pragma unroll
            for (int n = 0; n < 4; n++) bv[n] = Bsm[kk][tx * 4 + n];
            #pragma unroll
            for (int m = 0; m < 4; m++)
                #pragma unroll
                for (int n = 0; n < 4; n++) acc[m][n] += av[m] * bv[n];
        }
        __syncthreads();
    }
    #pragma unroll
    for (int m = 0; m < 4; m++)
        #pragma unroll
        for (int n = 0; n < 4; n++)
            g_conv[(b0 + ty * 4 + m) * HH + o0 + tx * 4 + n] = acc[m][n] + bc[o0 + tx * 4 + n];
}
__global__ void p_kernel(const float* __restrict__ Ws, const float* __restrict__ bs) {
    int b = blockIdx.x, s2 = threadIdx.x;
    float acc = bs[s2];
    for (int i = 0; i < HH; i++) acc += g_M[b * HH + i] * Ws[i * SS + s2];
    g_P[b * SS + s2] = fmaxf(acc, 0.0f);
}
__global__ void theme_kernel(const float* __restrict__ Wrs, const float* __restrict__ brs) {
    int b = blockIdx.x, o = threadIdx.x;
    float acc = brs[o];
    #pragma unroll 8
    for (int s2 = 0; s2 < SS; s2++) acc += g_P[b * SS + s2] * Wrs[s2 * HH + o];
    g_theme[b * HH + o] = sigmoidf(acc);
}
__global__ void out_kernel(const float* __restrict__ Wo, const float* __restrict__ bo,
                           float* __restrict__ out) {
    int b = blockIdx.x;
    __shared__ float red[128];
    const float* hfin = g_hist_h + ((TT - 1) % KKW) * BB * HH;
    float acc = 0.0f;
    for (int i = threadIdx.x; i < HH; i += 128) {
        float rnn = g_theme[b * HH + i] * g_conv[b * HH + i] + hfin[b * HH + i];
        acc += rnn * Wo[i];
    }
    red[threadIdx.x] = acc;
    __syncthreads();
    for (int s = 64; s > 0; s >>= 1) {
        if (threadIdx.x < s) red[threadIdx.x] += red[threadIdx.x + s];
        __syncthreads();
    }
    if (threadIdx.x == 0) out[b] = sigmoidf(red[0] + bo[0]);
}

// ---------- host ----------
extern "C" void kernel_launch(void* const* d_in, const int* in_sizes, int n_in,
                              void* d_out, int out_size)
{
    (void)in_sizes; (void)n_in; (void)out_size;
    const float* x   = (const float*)d_in[0];
    const float* Wk  = (const float*)d_in[1];
    const float* bk  = (const float*)d_in[2];
    const float* Wr  = (const float*)d_in[3];
    const float* br  = (const float*)d_in[4];
    const float* Ws  = (const float*)d_in[5];
    const float* bs  = (const float*)d_in[6];
    const float* Wrs = (const float*)d_in[7];
    const float* brs = (const float*)d_in[8];
    const float* Wc  = (const float*)d_in[9];
    const float* bc  = (const float*)d_in[10];
    const float* Wo  = (const float*)d_in[11];
    const float* bo  = (const float*)d_in[12];

    cudaFuncSetAttribute(stage_persistent, cudaFuncAttributeMaxDynamicSharedMemorySize, SMEM_BYTES);
    cudaFuncSetAttribute(xk_mma, cudaFuncAttributeMaxDynamicSharedMemorySize, PSMEM);

    bias_kernel<<<(GG + 255) / 256, 256>>>(Wk, bk, Wr, br);
    init_state_kernel<<<(BB * HH + 255) / 256, 256>>>();
    wct_kernel<<<(KKW * HH * HH + 255) / 256, 256>>>(Wc);
    xp_kernel<<<dim3(FF / 32, BB / 32, TT), dim3(32, 8)>>>(x);
    wkp_kernel<<<((FF/2) * GP + 255) / 256, 256>>>(Wk);
    xk_mma<<<dim3(2, 13, TT), 256, PSMEM>>>();

    stage_persistent<<<NBLK, 256, SMEM_BYTES>>>(Wr);

    dis_kernel<<<1, 256>>>();
    wh_kernel<<<(BB * HH + 255) / 256, 256>>>();
    conv_kernel<<<dim3(HH / 64, BB / 64), 256>>>(bc);
    p_kernel<<<BB, SS>>>(Ws, bs);
    theme_kernel<<<BB, HH>>>(Wrs, brs);
    out_kernel<<<BB, 128>>>(Wo, bo, (float*)d_out);
}